// round 5
// baseline (speedup 1.0000x reference)
#include <cuda_runtime.h>
#include <math.h>

#define BB 32
#define SS 512
#define HH 768
#define G4 3072
#define TT 9
#define VV 30522
#define MTOT (BB*SS)   // 16384

// ---------------- scratch (device globals; no cudaMalloc allowed) ----------------
__device__ float g_gates[(size_t)MTOT * G4];   // [n][3072] gate pre-activations (x-part + biases)
__device__ float g_h0[(size_t)MTOT * HH];      // layer0 hidden outputs [b*S+t][H]
__device__ float g_h1[(size_t)MTOT * HH];      // layer1 hidden outputs
__device__ float g_logp[MTOT * TT];            // log-softmax emissions
__device__ int   g_ids[MTOT];
__device__ int   g_labels[MTOT];
__device__ float g_llh[BB];
__device__ int   g_lenbuf[BB];
__device__ unsigned g_bar;                     // global barrier counter (monotonic per layer)

// ---------------- int64/int32 auto-detect + convert (with clamping) ----------------
__global__ void convert_idx_k(const void* __restrict__ idsraw, const void* __restrict__ labraw) {
    int i = blockIdx.x * blockDim.x + threadIdx.x;
    const unsigned* w = (const unsigned*)idsraw;
    bool is64 = true;
#pragma unroll
    for (int k = 0; k < 16; k++) is64 = is64 && (w[2 * k + 1] == 0u);
    if (i < MTOT) {
        long long idv, lbv;
        if (is64) {
            idv = ((const long long*)idsraw)[i];
            lbv = ((const long long*)labraw)[i];
        } else {
            idv = ((const int*)idsraw)[i];
            lbv = ((const int*)labraw)[i];
        }
        int idi = (int)idv, lbi = (int)lbv;
        if (idi < 0) idi = 0; if (idi >= VV) idi = VV - 1;
        if (lbi < 0) lbi = 0; if (lbi >= TT) lbi = TT - 1;
        g_ids[i] = idi;
        g_labels[i] = lbi;
    }
}

__global__ void reset_bar_k() { g_bar = 0u; }

// ---------------- SGEMM: C[M,3072] = A[M,768] @ W[3072,768]^T + (b1+b2) ----------------
__global__ __launch_bounds__(256) void sgemm_gate_k(
    const float* __restrict__ A, int use_gather,
    const float* __restrict__ W,
    const float* __restrict__ b1, const float* __restrict__ b2,
    float* __restrict__ C)
{
    __shared__ float As[16][132];  // [kk][row], padded
    __shared__ float Bs[16][64];   // [kk][col]
    const int bn = blockIdx.x;     // 0..47 (N tiles of 64)
    const int bm = blockIdx.y;     // 0..127 (M tiles of 128)
    const int tid = threadIdx.x;
    const int tm = tid >> 4, tn = tid & 15;
    const int row0 = bm * 128;

    const int ar = tid >> 1;
    const int akk = (tid & 1) * 8;
    int grow = row0 + ar;
    if (use_gather) grow = g_ids[grow];
    const float* arow = A + (size_t)grow * HH;
    const int br = tid >> 2;
    const int bkk = (tid & 3) * 4;
    const float* wrow = W + (size_t)(bn * 64 + br) * HH + bkk;

    float acc[8][4];
#pragma unroll
    for (int i = 0; i < 8; i++)
#pragma unroll
        for (int j = 0; j < 4; j++) acc[i][j] = 0.f;

    for (int k0 = 0; k0 < HH; k0 += 16) {
        float4 a0 = *(const float4*)(arow + k0 + akk);
        float4 a1 = *(const float4*)(arow + k0 + akk + 4);
        float4 bv = *(const float4*)(wrow + k0);
        As[akk + 0][ar] = a0.x; As[akk + 1][ar] = a0.y; As[akk + 2][ar] = a0.z; As[akk + 3][ar] = a0.w;
        As[akk + 4][ar] = a1.x; As[akk + 5][ar] = a1.y; As[akk + 6][ar] = a1.z; As[akk + 7][ar] = a1.w;
        Bs[bkk + 0][br] = bv.x; Bs[bkk + 1][br] = bv.y; Bs[bkk + 2][br] = bv.z; Bs[bkk + 3][br] = bv.w;
        __syncthreads();
#pragma unroll
        for (int kk = 0; kk < 16; kk++) {
            float4 x0 = *(const float4*)&As[kk][tm * 8];
            float4 x1 = *(const float4*)&As[kk][tm * 8 + 4];
            float4 y  = *(const float4*)&Bs[kk][tn * 4];
            float av[8] = {x0.x, x0.y, x0.z, x0.w, x1.x, x1.y, x1.z, x1.w};
            float bvv[4] = {y.x, y.y, y.z, y.w};
#pragma unroll
            for (int i = 0; i < 8; i++)
#pragma unroll
                for (int j = 0; j < 4; j++) acc[i][j] = fmaf(av[i], bvv[j], acc[i][j]);
        }
        __syncthreads();
    }
    const int col = bn * 64 + tn * 4;
    float bsv[4];
#pragma unroll
    for (int j = 0; j < 4; j++) bsv[j] = b1[col + j] + b2[col + j];
#pragma unroll
    for (int i = 0; i < 8; i++) {
        int gm = row0 + tm * 8 + i;
        float4 o;
        o.x = acc[i][0] + bsv[0]; o.y = acc[i][1] + bsv[1];
        o.z = acc[i][2] + bsv[2]; o.w = acc[i][3] + bsv[3];
        *(float4*)&C[(size_t)gm * G4 + col] = o;
    }
}

// ---------------- Persistent LSTM layer: all 512 steps in ONE kernel ----------------
__global__ __launch_bounds__(192) void lstm_seq_k(
    const float* __restrict__ Whh, float* __restrict__ hbuf)
{
    extern __shared__ float hs[];  // [768][33] transposed h_prev
    const int tid = threadIdx.x;
    const int warp = tid >> 5, lane = tid & 31;
    const int j = blockIdx.x * 6 + warp;   // 0..767
    const float4* wi = (const float4*)(Whh + (size_t)j * HH);
    const float4* wf = (const float4*)(Whh + (size_t)(HH + j) * HH);
    const float4* wg = (const float4*)(Whh + (size_t)(2 * HH + j) * HH);
    const float4* wo = (const float4*)(Whh + (size_t)(3 * HH + j) * HH);
    float c = 0.f;

    for (int t = 0; t < SS; t++) {
        if (t > 0) {
            const int kb = tid * 4;
#pragma unroll 8
            for (int b = 0; b < BB; b++) {
                float4 v = __ldcg((const float4*)(hbuf + ((size_t)(b * SS + t - 1)) * HH) + tid);
                hs[(kb + 0) * 33 + b] = v.x; hs[(kb + 1) * 33 + b] = v.y;
                hs[(kb + 2) * 33 + b] = v.z; hs[(kb + 3) * 33 + b] = v.w;
            }
            __syncthreads();
        }
        const size_t gb = ((size_t)(lane * SS + t)) * G4;
        float ai = g_gates[gb + j];
        float af = g_gates[gb + HH + j];
        float ag = g_gates[gb + 2 * HH + j];
        float ao = g_gates[gb + 3 * HH + j];
        if (t > 0) {
#pragma unroll 4
            for (int kc = 0; kc < 192; kc++) {
                float4 vi = wi[kc], vf = wf[kc], vg = wg[kc], vo = wo[kc];
                int k4 = kc * 4;
                float h0 = hs[(k4 + 0) * 33 + lane];
                float h1 = hs[(k4 + 1) * 33 + lane];
                float h2 = hs[(k4 + 2) * 33 + lane];
                float h3 = hs[(k4 + 3) * 33 + lane];
                ai = fmaf(vi.x, h0, ai); ai = fmaf(vi.y, h1, ai); ai = fmaf(vi.z, h2, ai); ai = fmaf(vi.w, h3, ai);
                af = fmaf(vf.x, h0, af); af = fmaf(vf.y, h1, af); af = fmaf(vf.z, h2, af); af = fmaf(vf.w, h3, af);
                ag = fmaf(vg.x, h0, ag); ag = fmaf(vg.y, h1, ag); ag = fmaf(vg.z, h2, ag); ag = fmaf(vg.w, h3, ag);
                ao = fmaf(vo.x, h0, ao); ao = fmaf(vo.y, h1, ao); ao = fmaf(vo.z, h2, ao); ao = fmaf(vo.w, h3, ao);
            }
        }
        float iv = 1.f / (1.f + expf(-ai));
        float fv = 1.f / (1.f + expf(-af));
        float gv = tanhf(ag);
        float ov = 1.f / (1.f + expf(-ao));
        c = fv * c + iv * gv;
        float hn = ov * tanhf(c);
        hbuf[((size_t)(lane * SS + t)) * HH + j] = hn;

        if (t + 1 < SS) {
            __threadfence();
            __syncthreads();
            if (tid == 0) {
                atomicAdd(&g_bar, 1u);
                const unsigned target = (unsigned)(t + 1) * gridDim.x;
                while (*((volatile unsigned*)&g_bar) < target) __nanosleep(64);
            }
            __syncthreads();
            __threadfence();
        }
    }
}

// ---------------- logits + log_softmax ----------------
__global__ __launch_bounds__(256) void logits_k(
    const float* __restrict__ h, const float* __restrict__ Wout, const float* __restrict__ bout)
{
    const int warp = threadIdx.x >> 5, lane = threadIdx.x & 31;
    const int n = blockIdx.x * 8 + warp;   // 0..16383
    float a[24];
#pragma unroll
    for (int c = 0; c < 6; c++) {
        float4 v = *(const float4*)(h + (size_t)n * HH + c * 128 + lane * 4);
        a[c * 4 + 0] = v.x; a[c * 4 + 1] = v.y; a[c * 4 + 2] = v.z; a[c * 4 + 3] = v.w;
    }
    float lg[TT];
#pragma unroll
    for (int t = 0; t < TT; t++) {
        float s = 0.f;
#pragma unroll
        for (int c = 0; c < 6; c++) {
            float4 w = *(const float4*)(Wout + (size_t)t * HH + c * 128 + lane * 4);
            s = fmaf(w.x, a[c * 4 + 0], s); s = fmaf(w.y, a[c * 4 + 1], s);
            s = fmaf(w.z, a[c * 4 + 2], s); s = fmaf(w.w, a[c * 4 + 3], s);
        }
#pragma unroll
        for (int o = 16; o; o >>= 1) s += __shfl_xor_sync(0xffffffffu, s, o);
        lg[t] = s + bout[t];
    }
    float m = lg[0];
#pragma unroll
    for (int t = 1; t < TT; t++) m = fmaxf(m, lg[t]);
    float se = 0.f;
#pragma unroll
    for (int t = 0; t < TT; t++) se += expf(lg[t] - m);
    float ls = m + logf(se);
    if (lane < TT) g_logp[(size_t)n * TT + lane] = lg[lane] - ls;
}

// ---------------- CRF NLL forward (warp per batch) ----------------
__global__ __launch_bounds__(128) void crf_forward_k(
    const int* __restrict__ amask,
    const float* __restrict__ start_t, const float* __restrict__ end_t,
    const float* __restrict__ trans)
{
    __shared__ float ts[TT * TT];
    if (threadIdx.x < TT * TT) ts[threadIdx.x] = trans[threadIdx.x];
    __syncthreads();
    const int w = threadIdx.x >> 5, lane = threadIdx.x & 31;
    const int b = blockIdx.x * 4 + w;
    const int* tg = g_labels + b * SS;
    const int* mk = amask + b * SS;
    const float* em = g_logp + (size_t)b * SS * TT;

    int cnt = 0; float num = 0.f;
    for (int s = lane; s < SS; s += 32) {
        int m = mk[s]; cnt += m;
        if (s > 0 && m) num += ts[tg[s - 1] * TT + tg[s]] + em[s * TT + tg[s]];
    }
    if (lane == 0) num += start_t[tg[0]] + em[tg[0]];
#pragma unroll
    for (int o = 16; o; o >>= 1) {
        num += __shfl_xor_sync(0xffffffffu, num, o);
        cnt += __shfl_xor_sync(0xffffffffu, cnt, o);
    }
    if (lane == 0) num += end_t[tg[cnt - 1]];
    num = __shfl_sync(0xffffffffu, num, 0);

    const int j = lane;
    float score = (j < TT) ? start_t[j] + em[j] : -1e30f;
    for (int s = 1; s < SS; s++) {
        float v[TT];
#pragma unroll
        for (int i = 0; i < TT; i++) v[i] = __shfl_sync(0xffffffffu, score, i);
        if (mk[s]) {
            if (j < TT) {
                float vv[TT], m2 = -1e30f;
#pragma unroll
                for (int i = 0; i < TT; i++) { vv[i] = v[i] + ts[i * TT + j]; m2 = fmaxf(m2, vv[i]); }
                float ssum = 0.f;
#pragma unroll
                for (int i = 0; i < TT; i++) ssum += expf(vv[i] - m2);
                score = m2 + logf(ssum) + em[s * TT + j];
            }
        }
    }
    float sc2 = (j < TT) ? score + end_t[j] : -1e30f;
    float vv[TT];
#pragma unroll
    for (int i = 0; i < TT; i++) vv[i] = __shfl_sync(0xffffffffu, sc2, i);
    if (lane == 0) {
        float m2 = vv[0];
#pragma unroll
        for (int i = 1; i < TT; i++) m2 = fmaxf(m2, vv[i]);
        float ssum = 0.f;
#pragma unroll
        for (int i = 0; i < TT; i++) ssum += expf(vv[i] - m2);
        float denom = m2 + logf(ssum);
        g_llh[b] = num - denom;
        g_lenbuf[b] = cnt;
    }
}

// ---------------- Viterbi decode (warp per batch, bp in smem), float32 output ----------------
__global__ __launch_bounds__(128) void viterbi_k(
    const int* __restrict__ amask,
    const float* __restrict__ start_t, const float* __restrict__ end_t,
    const float* __restrict__ trans, float* __restrict__ outp, int navail)
{
    __shared__ float ts[TT * TT];
    __shared__ unsigned char bp[4][SS][TT];
    if (threadIdx.x < TT * TT) ts[threadIdx.x] = trans[threadIdx.x];
    __syncthreads();
    const int w = threadIdx.x >> 5, lane = threadIdx.x & 31;
    const int b = blockIdx.x * 4 + w;
    const int* mk = amask + b * SS;
    const float* em = g_logp + (size_t)b * SS * TT;
    const int j = lane;

    float score = (j < TT) ? start_t[j] + em[j] : -1e30f;
    for (int s = 1; s < SS; s++) {
        float v[TT];
#pragma unroll
        for (int i = 0; i < TT; i++) v[i] = __shfl_sync(0xffffffffu, score, i);
        if (j < TT) {
            int bi = j;
            if (mk[s]) {
                float best = v[0] + ts[0 * TT + j]; bi = 0;
#pragma unroll
                for (int i = 1; i < TT; i++) {
                    float cc = v[i] + ts[i * TT + j];
                    if (cc > best) { best = cc; bi = i; }
                }
                score = best + em[s * TT + j];
            }
            bp[w][s][j] = (unsigned char)bi;
        }
    }
    float sc2 = (j < TT) ? score + end_t[j] : -1e30f;
    float vv[TT];
#pragma unroll
    for (int i = 0; i < TT; i++) vv[i] = __shfl_sync(0xffffffffu, sc2, i);
    if (lane == 0) {
        int tag = 0; float best = vv[0];
#pragma unroll
        for (int i = 1; i < TT; i++) if (vv[i] > best) { best = vv[i]; tag = i; }
        for (int s = SS - 1; s >= 1; s--) {
            int idx = b * SS + s;
            if (idx < navail) outp[idx] = mk[s] ? (float)tag : 0.0f;
            tag = (int)bp[w][s][tag];
        }
        if (b * SS < navail) outp[b * SS] = mk[0] ? (float)tag : 0.0f;
    }
}

// ---------------- finalize loss (float32) ----------------
__global__ void finalize32_k(float* __restrict__ out) {
    const int lane = threadIdx.x;
    float llh = g_llh[lane];
    int len = g_lenbuf[lane];
#pragma unroll
    for (int o = 16; o; o >>= 1) {
        llh += __shfl_xor_sync(0xffffffffu, llh, o);
        len += __shfl_xor_sync(0xffffffffu, len, o);
    }
    if (lane == 0) out[0] = (float)(-(double)llh / (double)len);
}

// ---------------- launch ----------------
extern "C" void kernel_launch(void* const* d_in, const int* in_sizes, int n_in,
                              void* d_out, int out_size) {
    (void)in_sizes; (void)n_in;
    const void* ids    = d_in[0];
    const int*  amask  = (const int*)d_in[1];
    const void* labels = d_in[2];
    const float* emb   = (const float*)d_in[3];
    const float* Wih0  = (const float*)d_in[4];
    const float* Whh0  = (const float*)d_in[5];
    const float* bih0  = (const float*)d_in[6];
    const float* bhh0  = (const float*)d_in[7];
    const float* Wih1  = (const float*)d_in[8];
    const float* Whh1  = (const float*)d_in[9];
    const float* bih1  = (const float*)d_in[10];
    const float* bhh1  = (const float*)d_in[11];
    const float* Wout  = (const float*)d_in[12];
    const float* bout  = (const float*)d_in[13];
    const float* start_t = (const float*)d_in[14];
    const float* end_t   = (const float*)d_in[15];
    const float* trans   = (const float*)d_in[16];
    float* out = (float*)d_out;

    void *p_gates, *p_h0, *p_h1;
    cudaGetSymbolAddress(&p_gates, g_gates);
    cudaGetSymbolAddress(&p_h0, g_h0);
    cudaGetSymbolAddress(&p_h1, g_h1);

    const int lstm_smem = 768 * 33 * 4;  // 101376 bytes
    cudaFuncSetAttribute(lstm_seq_k, cudaFuncAttributeMaxDynamicSharedMemorySize, lstm_smem);

    convert_idx_k<<<64, 256>>>(ids, labels);

    dim3 ggrid(48, 128);
    sgemm_gate_k<<<ggrid, 256>>>(emb, 1, Wih0, bih0, bhh0, (float*)p_gates);
    reset_bar_k<<<1, 1>>>();
    lstm_seq_k<<<128, 192, lstm_smem>>>(Whh0, (float*)p_h0);
    sgemm_gate_k<<<ggrid, 256>>>((const float*)p_h0, 0, Wih1, bih1, bhh1, (float*)p_gates);
    reset_bar_k<<<1, 1>>>();
    lstm_seq_k<<<128, 192, lstm_smem>>>(Whh1, (float*)p_h1);

    logits_k<<<2048, 256>>>((const float*)p_h1, Wout, bout);
    crf_forward_k<<<8, 128>>>(amask, start_t, end_t, trans);

    if (out_size >= 1 + MTOT) {
        // combined float32 layout: [loss, preds x 16384]
        viterbi_k<<<8, 128>>>(amask, start_t, end_t, trans, out + 1, out_size - 1);
    }
    finalize32_k<<<1, 32>>>(out);
}

// round 6
// speedup vs baseline: 1.7694x; 1.7694x over previous
#include <cuda_runtime.h>
#include <math.h>

#define BB 32
#define SS 512
#define HH 768
#define G4 3072
#define TT 9
#define VV 30522
#define MTOT (BB*SS)   // 16384
#define HT_STRIDE (HH*BB)  // 24576 floats per timestep

// ---------------- scratch (device globals; no cudaMalloc allowed) ----------------
__device__ float g_gates[(size_t)MTOT * G4];   // [n][3072] gate pre-activations (x-part + biases)
__device__ float g_h0[(size_t)MTOT * HH];      // layer0 hidden outputs [b*S+t][H]
__device__ float g_h1[(size_t)MTOT * HH];      // layer1 hidden outputs
__device__ float g_hT[(size_t)SS * HT_STRIDE]; // transposed hidden [t][j][b]
__device__ float g_logp[MTOT * TT];            // log-softmax emissions
__device__ int   g_ids[MTOT];
__device__ int   g_labels[MTOT];
__device__ float g_llh[BB];
__device__ int   g_lenbuf[BB];
__device__ unsigned g_bar;                     // global barrier counter (monotonic per layer)

// ---------------- int64/int32 auto-detect + convert (with clamping) ----------------
__global__ void convert_idx_k(const void* __restrict__ idsraw, const void* __restrict__ labraw) {
    int i = blockIdx.x * blockDim.x + threadIdx.x;
    const unsigned* w = (const unsigned*)idsraw;
    bool is64 = true;
#pragma unroll
    for (int k = 0; k < 16; k++) is64 = is64 && (w[2 * k + 1] == 0u);
    if (i < MTOT) {
        long long idv, lbv;
        if (is64) {
            idv = ((const long long*)idsraw)[i];
            lbv = ((const long long*)labraw)[i];
        } else {
            idv = ((const int*)idsraw)[i];
            lbv = ((const int*)labraw)[i];
        }
        int idi = (int)idv, lbi = (int)lbv;
        if (idi < 0) idi = 0; if (idi >= VV) idi = VV - 1;
        if (lbi < 0) lbi = 0; if (lbi >= TT) lbi = TT - 1;
        g_ids[i] = idi;
        g_labels[i] = lbi;
    }
}

__global__ void reset_bar_k() { g_bar = 0u; }

// ---------------- SGEMM: C[M,3072] = A[M,768] @ W[3072,768]^T + (b1+b2) ----------------
__global__ __launch_bounds__(256) void sgemm_gate_k(
    const float* __restrict__ A, int use_gather,
    const float* __restrict__ W,
    const float* __restrict__ b1, const float* __restrict__ b2,
    float* __restrict__ C)
{
    __shared__ float As[16][132];  // [kk][row], padded
    __shared__ float Bs[16][64];   // [kk][col]
    const int bn = blockIdx.x;     // 0..47 (N tiles of 64)
    const int bm = blockIdx.y;     // 0..127 (M tiles of 128)
    const int tid = threadIdx.x;
    const int tm = tid >> 4, tn = tid & 15;
    const int row0 = bm * 128;

    const int ar = tid >> 1;
    const int akk = (tid & 1) * 8;
    int grow = row0 + ar;
    if (use_gather) grow = g_ids[grow];
    const float* arow = A + (size_t)grow * HH;
    const int br = tid >> 2;
    const int bkk = (tid & 3) * 4;
    const float* wrow = W + (size_t)(bn * 64 + br) * HH + bkk;

    float acc[8][4];
#pragma unroll
    for (int i = 0; i < 8; i++)
#pragma unroll
        for (int j = 0; j < 4; j++) acc[i][j] = 0.f;

    for (int k0 = 0; k0 < HH; k0 += 16) {
        float4 a0 = *(const float4*)(arow + k0 + akk);
        float4 a1 = *(const float4*)(arow + k0 + akk + 4);
        float4 bv = *(const float4*)(wrow + k0);
        As[akk + 0][ar] = a0.x; As[akk + 1][ar] = a0.y; As[akk + 2][ar] = a0.z; As[akk + 3][ar] = a0.w;
        As[akk + 4][ar] = a1.x; As[akk + 5][ar] = a1.y; As[akk + 6][ar] = a1.z; As[akk + 7][ar] = a1.w;
        Bs[bkk + 0][br] = bv.x; Bs[bkk + 1][br] = bv.y; Bs[bkk + 2][br] = bv.z; Bs[bkk + 3][br] = bv.w;
        __syncthreads();
#pragma unroll
        for (int kk = 0; kk < 16; kk++) {
            float4 x0 = *(const float4*)&As[kk][tm * 8];
            float4 x1 = *(const float4*)&As[kk][tm * 8 + 4];
            float4 y  = *(const float4*)&Bs[kk][tn * 4];
            float av[8] = {x0.x, x0.y, x0.z, x0.w, x1.x, x1.y, x1.z, x1.w};
            float bvv[4] = {y.x, y.y, y.z, y.w};
#pragma unroll
            for (int i = 0; i < 8; i++)
#pragma unroll
                for (int j = 0; j < 4; j++) acc[i][j] = fmaf(av[i], bvv[j], acc[i][j]);
        }
        __syncthreads();
    }
    const int col = bn * 64 + tn * 4;
    float bsv[4];
#pragma unroll
    for (int j = 0; j < 4; j++) bsv[j] = b1[col + j] + b2[col + j];
#pragma unroll
    for (int i = 0; i < 8; i++) {
        int gm = row0 + tm * 8 + i;
        float4 o;
        o.x = acc[i][0] + bsv[0]; o.y = acc[i][1] + bsv[1];
        o.z = acc[i][2] + bsv[2]; o.w = acc[i][3] + bsv[3];
        *(float4*)&C[(size_t)gm * G4 + col] = o;
    }
}

// ---------------- Persistent LSTM layer, high-occupancy version ----------------
// 128 blocks x 768 threads (24 warps). warp w: jloc = w>>2 (6 per block), gate = w&3.
// Lanes = batch. Each warp computes one (j,gate) dot product over K=768.
// Gates meet in smem; warps with gate==0 do activations and hold cell state c.
// h exchanged via transposed global g_hT[t][j][b]; staged into smem each step.
#define HS_STRIDE 772   // 768 + 4: LDS.128 conflict-free (per-phase banks distinct)
#define SMEM_LSTM_BYTES 118784  // > 227KB/2 -> forces 1 block/SM (barrier safety)

__global__ __launch_bounds__(768) void lstm_seq_k(
    const float* __restrict__ Whh, float* __restrict__ hT)
{
    extern __shared__ float sm[];
    float* hs = sm;                        // [32][HS_STRIDE] h_prev, [b][k]
    float* sm_dot = sm + 32 * HS_STRIDE;   // [24][33]
    const int tid = threadIdx.x;
    const int w = tid >> 5, lane = tid & 31;
    const int jloc = w >> 2, gate = w & 3;
    const int j = blockIdx.x * 6 + jloc;
    const float4* wrow = (const float4*)(Whh + ((size_t)gate * HH + j) * HH);
    const bool act = (gate == 0);
    float c = 0.f;

    for (int t = 0; t < SS; t++) {
        // gate pre-activation (x-part + biases); diverged load, latency hidden by main loop
        float pre = g_gates[((size_t)(lane * SS + t)) * G4 + (size_t)gate * HH + j];

        if (t > 0) {
            // stage h_{t-1} from g_hT[t-1][j][b] into hs[b][j] (transpose in smem)
#pragma unroll
            for (int r = 0; r < 8; r++) {
                int idx = r * 3072 + tid * 4;            // [j*32 + b], b0 multiple of 4
                float4 v = __ldcg((const float4*)(hT + (size_t)(t - 1) * HT_STRIDE + idx));
                int jj = idx >> 5, b0 = idx & 31;
                hs[(b0 + 0) * HS_STRIDE + jj] = v.x;
                hs[(b0 + 1) * HS_STRIDE + jj] = v.y;
                hs[(b0 + 2) * HS_STRIDE + jj] = v.z;
                hs[(b0 + 3) * HS_STRIDE + jj] = v.w;
            }
            __syncthreads();
        }

        float4 acc = make_float4(0.f, 0.f, 0.f, 0.f);
        if (t > 0) {
            const float* hrow = hs + lane * HS_STRIDE;
#pragma unroll 8
            for (int kc = 0; kc < 192; kc++) {
                float4 wv = wrow[kc];                         // uniform, L1-resident
                float4 hv = *(const float4*)(hrow + kc * 4);  // LDS.128 conflict-free
                acc.x = fmaf(wv.x, hv.x, acc.x);
                acc.y = fmaf(wv.y, hv.y, acc.y);
                acc.z = fmaf(wv.z, hv.z, acc.z);
                acc.w = fmaf(wv.w, hv.w, acc.w);
            }
        }
        float dot = (acc.x + acc.y) + (acc.z + acc.w) + pre;
        sm_dot[w * 33 + lane] = dot;
        __syncthreads();

        if (act) {
            float ai = sm_dot[(w + 0) * 33 + lane];
            float af = sm_dot[(w + 1) * 33 + lane];
            float ag = sm_dot[(w + 2) * 33 + lane];
            float ao = sm_dot[(w + 3) * 33 + lane];
            float iv = 1.f / (1.f + expf(-ai));
            float fv = 1.f / (1.f + expf(-af));
            float gv = tanhf(ag);
            float ov = 1.f / (1.f + expf(-ao));
            c = fv * c + iv * gv;
            float hn = ov * tanhf(c);
            hT[(size_t)t * HT_STRIDE + j * 32 + lane] = hn;   // coalesced
        }

        if (t + 1 < SS) {
            __threadfence();     // h writes visible before flag
            __syncthreads();
            if (tid == 0) {
                atomicAdd(&g_bar, 1u);
                const unsigned target = (unsigned)(t + 1) * gridDim.x;
                while (*((volatile unsigned*)&g_bar) < target) __nanosleep(64);
            }
            __syncthreads();
        }
    }
}

// ---------------- transpose g_hT[t][j][b] -> h[n=b*S+t][j] ----------------
__global__ __launch_bounds__(768) void transpose_h_k(
    const float* __restrict__ hT, float* __restrict__ hout)
{
    extern __shared__ float sm[];   // [768][33]
    const int t = blockIdx.x;
    const int tid = threadIdx.x;
#pragma unroll
    for (int r = 0; r < 32; r++) {
        int idx = r * 768 + tid;          // j*32 + b
        float v = __ldcg(hT + (size_t)t * HT_STRIDE + idx);
        sm[(idx >> 5) * 33 + (idx & 31)] = v;
    }
    __syncthreads();
#pragma unroll
    for (int b = 0; b < 32; b++) {
        hout[((size_t)(b * SS + t)) * HH + tid] = sm[tid * 33 + b];
    }
}

// ---------------- logits + log_softmax ----------------
__global__ __launch_bounds__(256) void logits_k(
    const float* __restrict__ h, const float* __restrict__ Wout, const float* __restrict__ bout)
{
    const int warp = threadIdx.x >> 5, lane = threadIdx.x & 31;
    const int n = blockIdx.x * 8 + warp;   // 0..16383
    float a[24];
#pragma unroll
    for (int c = 0; c < 6; c++) {
        float4 v = *(const float4*)(h + (size_t)n * HH + c * 128 + lane * 4);
        a[c * 4 + 0] = v.x; a[c * 4 + 1] = v.y; a[c * 4 + 2] = v.z; a[c * 4 + 3] = v.w;
    }
    float lg[TT];
#pragma unroll
    for (int t = 0; t < TT; t++) {
        float s = 0.f;
#pragma unroll
        for (int c = 0; c < 6; c++) {
            float4 w = *(const float4*)(Wout + (size_t)t * HH + c * 128 + lane * 4);
            s = fmaf(w.x, a[c * 4 + 0], s); s = fmaf(w.y, a[c * 4 + 1], s);
            s = fmaf(w.z, a[c * 4 + 2], s); s = fmaf(w.w, a[c * 4 + 3], s);
        }
#pragma unroll
        for (int o = 16; o; o >>= 1) s += __shfl_xor_sync(0xffffffffu, s, o);
        lg[t] = s + bout[t];
    }
    float m = lg[0];
#pragma unroll
    for (int t = 1; t < TT; t++) m = fmaxf(m, lg[t]);
    float se = 0.f;
#pragma unroll
    for (int t = 0; t < TT; t++) se += expf(lg[t] - m);
    float ls = m + logf(se);
    if (lane < TT) g_logp[(size_t)n * TT + lane] = lg[lane] - ls;
}

// ---------------- CRF NLL forward (warp per batch) ----------------
__global__ __launch_bounds__(128) void crf_forward_k(
    const int* __restrict__ amask,
    const float* __restrict__ start_t, const float* __restrict__ end_t,
    const float* __restrict__ trans)
{
    __shared__ float ts[TT * TT];
    if (threadIdx.x < TT * TT) ts[threadIdx.x] = trans[threadIdx.x];
    __syncthreads();
    const int w = threadIdx.x >> 5, lane = threadIdx.x & 31;
    const int b = blockIdx.x * 4 + w;
    const int* tg = g_labels + b * SS;
    const int* mk = amask + b * SS;
    const float* em = g_logp + (size_t)b * SS * TT;

    int cnt = 0; float num = 0.f;
    for (int s = lane; s < SS; s += 32) {
        int m = mk[s]; cnt += m;
        if (s > 0 && m) num += ts[tg[s - 1] * TT + tg[s]] + em[s * TT + tg[s]];
    }
    if (lane == 0) num += start_t[tg[0]] + em[tg[0]];
#pragma unroll
    for (int o = 16; o; o >>= 1) {
        num += __shfl_xor_sync(0xffffffffu, num, o);
        cnt += __shfl_xor_sync(0xffffffffu, cnt, o);
    }
    if (lane == 0) num += end_t[tg[cnt - 1]];
    num = __shfl_sync(0xffffffffu, num, 0);

    const int j = lane;
    float score = (j < TT) ? start_t[j] + em[j] : -1e30f;
    for (int s = 1; s < SS; s++) {
        float v[TT];
#pragma unroll
        for (int i = 0; i < TT; i++) v[i] = __shfl_sync(0xffffffffu, score, i);
        if (mk[s]) {
            if (j < TT) {
                float vv[TT], m2 = -1e30f;
#pragma unroll
                for (int i = 0; i < TT; i++) { vv[i] = v[i] + ts[i * TT + j]; m2 = fmaxf(m2, vv[i]); }
                float ssum = 0.f;
#pragma unroll
                for (int i = 0; i < TT; i++) ssum += expf(vv[i] - m2);
                score = m2 + logf(ssum) + em[s * TT + j];
            }
        }
    }
    float sc2 = (j < TT) ? score + end_t[j] : -1e30f;
    float vv[TT];
#pragma unroll
    for (int i = 0; i < TT; i++) vv[i] = __shfl_sync(0xffffffffu, sc2, i);
    if (lane == 0) {
        float m2 = vv[0];
#pragma unroll
        for (int i = 1; i < TT; i++) m2 = fmaxf(m2, vv[i]);
        float ssum = 0.f;
#pragma unroll
        for (int i = 0; i < TT; i++) ssum += expf(vv[i] - m2);
        float denom = m2 + logf(ssum);
        g_llh[b] = num - denom;
        g_lenbuf[b] = cnt;
    }
}

// ---------------- Viterbi decode (warp per batch, bp in smem), float32 output ----------------
__global__ __launch_bounds__(128) void viterbi_k(
    const int* __restrict__ amask,
    const float* __restrict__ start_t, const float* __restrict__ end_t,
    const float* __restrict__ trans, float* __restrict__ outp, int navail)
{
    __shared__ float ts[TT * TT];
    __shared__ unsigned char bp[4][SS][TT];
    if (threadIdx.x < TT * TT) ts[threadIdx.x] = trans[threadIdx.x];
    __syncthreads();
    const int w = threadIdx.x >> 5, lane = threadIdx.x & 31;
    const int b = blockIdx.x * 4 + w;
    const int* mk = amask + b * SS;
    const float* em = g_logp + (size_t)b * SS * TT;
    const int j = lane;

    float score = (j < TT) ? start_t[j] + em[j] : -1e30f;
    for (int s = 1; s < SS; s++) {
        float v[TT];
#pragma unroll
        for (int i = 0; i < TT; i++) v[i] = __shfl_sync(0xffffffffu, score, i);
        if (j < TT) {
            int bi = j;
            if (mk[s]) {
                float best = v[0] + ts[0 * TT + j]; bi = 0;
#pragma unroll
                for (int i = 1; i < TT; i++) {
                    float cc = v[i] + ts[i * TT + j];
                    if (cc > best) { best = cc; bi = i; }
                }
                score = best + em[s * TT + j];
            }
            bp[w][s][j] = (unsigned char)bi;
        }
    }
    float sc2 = (j < TT) ? score + end_t[j] : -1e30f;
    float vv[TT];
#pragma unroll
    for (int i = 0; i < TT; i++) vv[i] = __shfl_sync(0xffffffffu, sc2, i);
    if (lane == 0) {
        int tag = 0; float best = vv[0];
#pragma unroll
        for (int i = 1; i < TT; i++) if (vv[i] > best) { best = vv[i]; tag = i; }
        for (int s = SS - 1; s >= 1; s--) {
            int idx = b * SS + s;
            if (idx < navail) outp[idx] = mk[s] ? (float)tag : 0.0f;
            tag = (int)bp[w][s][tag];
        }
        if (b * SS < navail) outp[b * SS] = mk[0] ? (float)tag : 0.0f;
    }
}

// ---------------- finalize loss (float32) ----------------
__global__ void finalize32_k(float* __restrict__ out) {
    const int lane = threadIdx.x;
    float llh = g_llh[lane];
    int len = g_lenbuf[lane];
#pragma unroll
    for (int o = 16; o; o >>= 1) {
        llh += __shfl_xor_sync(0xffffffffu, llh, o);
        len += __shfl_xor_sync(0xffffffffu, len, o);
    }
    if (lane == 0) out[0] = (float)(-(double)llh / (double)len);
}

// ---------------- launch ----------------
extern "C" void kernel_launch(void* const* d_in, const int* in_sizes, int n_in,
                              void* d_out, int out_size) {
    (void)in_sizes; (void)n_in;
    const void* ids    = d_in[0];
    const int*  amask  = (const int*)d_in[1];
    const void* labels = d_in[2];
    const float* emb   = (const float*)d_in[3];
    const float* Wih0  = (const float*)d_in[4];
    const float* Whh0  = (const float*)d_in[5];
    const float* bih0  = (const float*)d_in[6];
    const float* bhh0  = (const float*)d_in[7];
    const float* Wih1  = (const float*)d_in[8];
    const float* Whh1  = (const float*)d_in[9];
    const float* bih1  = (const float*)d_in[10];
    const float* bhh1  = (const float*)d_in[11];
    const float* Wout  = (const float*)d_in[12];
    const float* bout  = (const float*)d_in[13];
    const float* start_t = (const float*)d_in[14];
    const float* end_t   = (const float*)d_in[15];
    const float* trans   = (const float*)d_in[16];
    float* out = (float*)d_out;

    void *p_gates, *p_h0, *p_h1, *p_hT;
    cudaGetSymbolAddress(&p_gates, g_gates);
    cudaGetSymbolAddress(&p_h0, g_h0);
    cudaGetSymbolAddress(&p_h1, g_h1);
    cudaGetSymbolAddress(&p_hT, g_hT);

    cudaFuncSetAttribute(lstm_seq_k, cudaFuncAttributeMaxDynamicSharedMemorySize, SMEM_LSTM_BYTES);
    const int tsm = 768 * 33 * 4;  // 101376
    cudaFuncSetAttribute(transpose_h_k, cudaFuncAttributeMaxDynamicSharedMemorySize, tsm);

    convert_idx_k<<<64, 256>>>(ids, labels);

    dim3 ggrid(48, 128);
    // layer 0
    sgemm_gate_k<<<ggrid, 256>>>(emb, 1, Wih0, bih0, bhh0, (float*)p_gates);
    reset_bar_k<<<1, 1>>>();
    lstm_seq_k<<<128, 768, SMEM_LSTM_BYTES>>>(Whh0, (float*)p_hT);
    transpose_h_k<<<512, 768, tsm>>>((const float*)p_hT, (float*)p_h0);
    // layer 1
    sgemm_gate_k<<<ggrid, 256>>>((const float*)p_h0, 0, Wih1, bih1, bhh1, (float*)p_gates);
    reset_bar_k<<<1, 1>>>();
    lstm_seq_k<<<128, 768, SMEM_LSTM_BYTES>>>(Whh1, (float*)p_hT);
    transpose_h_k<<<512, 768, tsm>>>((const float*)p_hT, (float*)p_h1);

    logits_k<<<2048, 256>>>((const float*)p_h1, Wout, bout);
    crf_forward_k<<<8, 128>>>(amask, start_t, end_t, trans);

    if (out_size >= 1 + MTOT) {
        viterbi_k<<<8, 128>>>(amask, start_t, end_t, trans, out + 1, out_size - 1);
    }
    finalize32_k<<<1, 32>>>(out);
}

// round 8
// speedup vs baseline: 2.4523x; 1.3859x over previous
#include <cuda_runtime.h>
#include <math.h>

#define BB 32
#define SS 512
#define HH 768
#define G4 3072
#define TT 9
#define VV 30522
#define MTOT (BB*SS)       // 16384
#define HT_STRIDE (HH*BB)  // 24576 floats per timestep

typedef unsigned long long u64;

// packed fp32x2 FMA (sm_103a FFMA2)
#define FMA_F32X2(d, a, b, c) \
    asm("fma.rn.f32x2 %0, %1, %2, %3;" : "=l"(d) : "l"(a), "l"(b), "l"(c))
#define PACK_F32X2(out, lo, hi) \
    asm("mov.b64 %0, {%1, %2};" : "=l"(out) : "f"(lo), "f"(hi))
#define UNPACK_F32X2(lo, hi, in) \
    asm("mov.b64 {%0, %1}, %2;" : "=f"(lo), "=f"(hi) : "l"(in))

// ---------------- scratch (device globals; no cudaMalloc allowed) ----------------
__device__ float g_gates[(size_t)MTOT * G4];   // [n][3072] gate pre-activations (x-part + biases)
__device__ float g_h0[(size_t)MTOT * HH];      // layer0 hidden outputs [b*S+t][H]
__device__ float g_h1[(size_t)MTOT * HH];      // layer1 hidden outputs
__device__ float g_hT[(size_t)SS * HT_STRIDE]; // transposed hidden [t][j][b]
__device__ float g_logp[MTOT * TT];            // log-softmax emissions
__device__ int   g_ids[MTOT];
__device__ int   g_labels[MTOT];
__device__ float g_llh[BB];
__device__ int   g_lenbuf[BB];
__device__ unsigned g_bar;                     // global barrier counter (monotonic per layer)

// ---------------- int64/int32 auto-detect + convert (with clamping) ----------------
__global__ void convert_idx_k(const void* __restrict__ idsraw, const void* __restrict__ labraw) {
    int i = blockIdx.x * blockDim.x + threadIdx.x;
    const unsigned* w = (const unsigned*)idsraw;
    bool is64 = true;
#pragma unroll
    for (int k = 0; k < 16; k++) is64 = is64 && (w[2 * k + 1] == 0u);
    if (i < MTOT) {
        long long idv, lbv;
        if (is64) {
            idv = ((const long long*)idsraw)[i];
            lbv = ((const long long*)labraw)[i];
        } else {
            idv = ((const int*)idsraw)[i];
            lbv = ((const int*)labraw)[i];
        }
        int idi = (int)idv, lbi = (int)lbv;
        if (idi < 0) idi = 0; if (idi >= VV) idi = VV - 1;
        if (lbi < 0) lbi = 0; if (lbi >= TT) lbi = TT - 1;
        g_ids[i] = idi;
        g_labels[i] = lbi;
    }
}

__global__ void reset_bar_k() { g_bar = 0u; }

// ---------------- SGEMM (f32x2): C[M,3072] = A[M,768] @ W[3072,768]^T + (b1+b2) ----------------
__global__ __launch_bounds__(256) void sgemm_gate_k(
    const float* __restrict__ A, int use_gather,
    const float* __restrict__ W,
    const float* __restrict__ b1, const float* __restrict__ b2,
    float* __restrict__ C)
{
    __shared__ float As[16][132];  // [kk][row], padded
    __shared__ float Bs[16][64];   // [kk][col]
    const int bn = blockIdx.x;     // 0..47 (N tiles of 64)
    const int bm = blockIdx.y;     // 0..127 (M tiles of 128)
    const int tid = threadIdx.x;
    const int tm = tid >> 4, tn = tid & 15;
    const int row0 = bm * 128;

    const int ar = tid >> 1;
    const int akk = (tid & 1) * 8;
    int grow = row0 + ar;
    if (use_gather) grow = g_ids[grow];
    const float* arow = A + (size_t)grow * HH;
    const int br = tid >> 2;
    const int bkk = (tid & 3) * 4;
    const float* wrow = W + (size_t)(bn * 64 + br) * HH + bkk;

    u64 acc2[4][4];   // [row-pair][col]
#pragma unroll
    for (int p = 0; p < 4; p++)
#pragma unroll
        for (int q = 0; q < 4; q++) acc2[p][q] = 0ull;

    for (int k0 = 0; k0 < HH; k0 += 16) {
        float4 a0 = *(const float4*)(arow + k0 + akk);
        float4 a1 = *(const float4*)(arow + k0 + akk + 4);
        float4 bv = *(const float4*)(wrow + k0);
        As[akk + 0][ar] = a0.x; As[akk + 1][ar] = a0.y; As[akk + 2][ar] = a0.z; As[akk + 3][ar] = a0.w;
        As[akk + 4][ar] = a1.x; As[akk + 5][ar] = a1.y; As[akk + 6][ar] = a1.z; As[akk + 7][ar] = a1.w;
        Bs[bkk + 0][br] = bv.x; Bs[bkk + 1][br] = bv.y; Bs[bkk + 2][br] = bv.z; Bs[bkk + 3][br] = bv.w;
        __syncthreads();
#pragma unroll
        for (int kk = 0; kk < 16; kk++) {
            ulonglong2 av0 = *(const ulonglong2*)&As[kk][tm * 8];
            ulonglong2 av1 = *(const ulonglong2*)&As[kk][tm * 8 + 4];
            float4 y = *(const float4*)&Bs[kk][tn * 4];
            u64 ap[4] = {av0.x, av0.y, av1.x, av1.y};
            u64 bd[4];
            PACK_F32X2(bd[0], y.x, y.x);
            PACK_F32X2(bd[1], y.y, y.y);
            PACK_F32X2(bd[2], y.z, y.z);
            PACK_F32X2(bd[3], y.w, y.w);
#pragma unroll
            for (int p = 0; p < 4; p++)
#pragma unroll
                for (int q = 0; q < 4; q++)
                    FMA_F32X2(acc2[p][q], ap[p], bd[q], acc2[p][q]);
        }
        __syncthreads();
    }
    const int col = bn * 64 + tn * 4;
    float bsv[4];
#pragma unroll
    for (int q = 0; q < 4; q++) bsv[q] = b1[col + q] + b2[col + q];
#pragma unroll
    for (int p = 0; p < 4; p++) {
        float lo[4], hi[4];
#pragma unroll
        for (int q = 0; q < 4; q++) UNPACK_F32X2(lo[q], hi[q], acc2[p][q]);
        int gm0 = row0 + tm * 8 + 2 * p;
        float4 o0, o1;
        o0.x = lo[0] + bsv[0]; o0.y = lo[1] + bsv[1]; o0.z = lo[2] + bsv[2]; o0.w = lo[3] + bsv[3];
        o1.x = hi[0] + bsv[0]; o1.y = hi[1] + bsv[1]; o1.z = hi[2] + bsv[2]; o1.w = hi[3] + bsv[3];
        *(float4*)&C[(size_t)gm0 * G4 + col] = o0;
        *(float4*)&C[(size_t)(gm0 + 1) * G4 + col] = o1;
    }
}

// ---------------- Persistent LSTM layer (k-split, f32x2) ----------------
// 128 blocks x 768 threads (24 warps). warp w: jloc = w>>2, ks = w&3.
// Warp computes ALL 4 gate partial dots for j=blockIdx*6+jloc over k-chunk [ks*192, ks*192+192).
// Lane = batch. Partials exchanged in smem; gate-role-0 warps (w&3==0) do activations (c in regs).
#define HS_STRIDE 780   // conflict-free for both staging STS scatter and LDS.128 reads
#define EX_OFF (32 * HS_STRIDE)          // 24960 floats
#define SMEM_LSTM_BYTES 118784           // > 227KB/2 -> 1 block/SM (barrier co-residency)

__global__ __launch_bounds__(768) void lstm_seq_k(
    const float* __restrict__ Whh, float* __restrict__ hT)
{
    extern __shared__ float sm[];
    float* hs = sm;                  // [32][HS_STRIDE] h_prev, [b][k]
    float* ex = sm + EX_OFF;         // [6][4][4][33] partial dots
    const int tid = threadIdx.x;
    const int w = tid >> 5, lane = tid & 31;
    const int jloc = w >> 2, ks = w & 3;
    const int j = blockIdx.x * 6 + jloc;
    const int k0 = ks * 192;
    const bool act = (ks == 0);

    // weight row pointers for the 4 gates (this j, this k-chunk), as 128-bit pairs
    const ulonglong2* wr0 = (const ulonglong2*)(Whh + ((size_t)0 * HH + j) * HH + k0);
    const ulonglong2* wr1 = (const ulonglong2*)(Whh + ((size_t)1 * HH + j) * HH + k0);
    const ulonglong2* wr2 = (const ulonglong2*)(Whh + ((size_t)2 * HH + j) * HH + k0);
    const ulonglong2* wr3 = (const ulonglong2*)(Whh + ((size_t)3 * HH + j) * HH + k0);
    float c = 0.f;

    for (int t = 0; t < SS; t++) {
        // this warp's gate (=ks) preactivation for (batch=lane, t, j)
        float pre = g_gates[((size_t)(lane * SS + t)) * G4 + (size_t)ks * HH + j];

        if (t > 0) {
            // stage h_{t-1} from g_hT[t-1][j][b] into hs[b][k=j] (cross-SM: L2 reads)
#pragma unroll
            for (int r = 0; r < 8; r++) {
                int idx = r * 3072 + tid * 4;    // j*32 + b, b0 multiple of 4
                float4 v = __ldcg((const float4*)(hT + (size_t)(t - 1) * HT_STRIDE + idx));
                int jj = idx >> 5, b0 = idx & 31;
                hs[(b0 + 0) * HS_STRIDE + jj] = v.x;
                hs[(b0 + 1) * HS_STRIDE + jj] = v.y;
                hs[(b0 + 2) * HS_STRIDE + jj] = v.z;
                hs[(b0 + 3) * HS_STRIDE + jj] = v.w;
            }
            __syncthreads();
        }

        u64 a0l = 0, a0h = 0, a1l = 0, a1h = 0, a2l = 0, a2h = 0, a3l = 0, a3h = 0;
        if (t > 0) {
            const float* hrow = hs + lane * HS_STRIDE + k0;
#pragma unroll 8
            for (int kc = 0; kc < 48; kc++) {
                ulonglong2 hv = *(const ulonglong2*)(hrow + kc * 4);   // LDS.128 conflict-free
                ulonglong2 w0 = wr0[kc];  // uniform LDG.128, L1-resident
                ulonglong2 w1 = wr1[kc];
                ulonglong2 w2 = wr2[kc];
                ulonglong2 w3 = wr3[kc];
                FMA_F32X2(a0l, w0.x, hv.x, a0l); FMA_F32X2(a0h, w0.y, hv.y, a0h);
                FMA_F32X2(a1l, w1.x, hv.x, a1l); FMA_F32X2(a1h, w1.y, hv.y, a1h);
                FMA_F32X2(a2l, w2.x, hv.x, a2l); FMA_F32X2(a2h, w2.y, hv.y, a2h);
                FMA_F32X2(a3l, w3.x, hv.x, a3l); FMA_F32X2(a3h, w3.y, hv.y, a3h);
            }
        }
        // reduce pairs, add pre to this warp's own gate (=ks)
        float pd[4];
        {
            float l0, h0, l1, h1;
            UNPACK_F32X2(l0, h0, a0l); UNPACK_F32X2(l1, h1, a0h); pd[0] = (l0 + h0) + (l1 + h1);
            UNPACK_F32X2(l0, h0, a1l); UNPACK_F32X2(l1, h1, a1h); pd[1] = (l0 + h0) + (l1 + h1);
            UNPACK_F32X2(l0, h0, a2l); UNPACK_F32X2(l1, h1, a2h); pd[2] = (l0 + h0) + (l1 + h1);
            UNPACK_F32X2(l0, h0, a3l); UNPACK_F32X2(l1, h1, a3h); pd[3] = (l0 + h0) + (l1 + h1);
        }
        pd[ks] += pre;
#pragma unroll
        for (int g = 0; g < 4; g++)
            ex[((w * 4) + g) * 33 + lane] = pd[g];   // ex[jloc][ks][g][lane]
        __syncthreads();

        if (act) {
            // sum 4 k-split partials per gate: ex[jloc][0..3][g][lane]
            float gt[4];
#pragma unroll
            for (int g = 0; g < 4; g++) {
                float s = 0.f;
#pragma unroll
                for (int p = 0; p < 4; p++)
                    s += ex[(((jloc * 4 + p) * 4) + g) * 33 + lane];
                gt[g] = s;
            }
            float iv = 1.f / (1.f + expf(-gt[0]));
            float fv = 1.f / (1.f + expf(-gt[1]));
            float gv = tanhf(gt[2]);
            float ov = 1.f / (1.f + expf(-gt[3]));
            c = fv * c + iv * gv;
            float hn = ov * tanhf(c);
            hT[(size_t)t * HT_STRIDE + j * 32 + lane] = hn;   // coalesced
            __threadfence();   // release: h visible before barrier arrival
        }

        if (t + 1 < SS) {
            __syncthreads();
            if (tid == 0) {
                atomicAdd(&g_bar, 1u);
                const unsigned target = (unsigned)(t + 1) * gridDim.x;
                while (*((volatile unsigned*)&g_bar) < target) __nanosleep(64);
            }
            __syncthreads();
        }
    }
}

// ---------------- transpose g_hT[t][j][b] -> h[n=b*S+t][j] ----------------
__global__ __launch_bounds__(768) void transpose_h_k(
    const float* __restrict__ hT, float* __restrict__ hout)
{
    extern __shared__ float sm[];   // [768][33]
    const int t = blockIdx.x;
    const int tid = threadIdx.x;
#pragma unroll
    for (int r = 0; r < 32; r++) {
        int idx = r * 768 + tid;          // j*32 + b
        float v = __ldcg(hT + (size_t)t * HT_STRIDE + idx);
        sm[(idx >> 5) * 33 + (idx & 31)] = v;
    }
    __syncthreads();
#pragma unroll
    for (int b = 0; b < 32; b++) {
        hout[((size_t)(b * SS + t)) * HH + tid] = sm[tid * 33 + b];
    }
}

// ---------------- logits + log_softmax ----------------
__global__ __launch_bounds__(256) void logits_k(
    const float* __restrict__ h, const float* __restrict__ Wout, const float* __restrict__ bout)
{
    const int warp = threadIdx.x >> 5, lane = threadIdx.x & 31;
    const int n = blockIdx.x * 8 + warp;   // 0..16383
    float a[24];
#pragma unroll
    for (int c = 0; c < 6; c++) {
        float4 v = *(const float4*)(h + (size_t)n * HH + c * 128 + lane * 4);
        a[c * 4 + 0] = v.x; a[c * 4 + 1] = v.y; a[c * 4 + 2] = v.z; a[c * 4 + 3] = v.w;
    }
    float lg[TT];
#pragma unroll
    for (int t = 0; t < TT; t++) {
        float s = 0.f;
#pragma unroll
        for (int c = 0; c < 6; c++) {
            float4 w = *(const float4*)(Wout + (size_t)t * HH + c * 128 + lane * 4);
            s = fmaf(w.x, a[c * 4 + 0], s); s = fmaf(w.y, a[c * 4 + 1], s);
            s = fmaf(w.z, a[c * 4 + 2], s); s = fmaf(w.w, a[c * 4 + 3], s);
        }
#pragma unroll
        for (int o = 16; o; o >>= 1) s += __shfl_xor_sync(0xffffffffu, s, o);
        lg[t] = s + bout[t];
    }
    float m = lg[0];
#pragma unroll
    for (int t = 1; t < TT; t++) m = fmaxf(m, lg[t]);
    float se = 0.f;
#pragma unroll
    for (int t = 0; t < TT; t++) se += expf(lg[t] - m);
    float ls = m + logf(se);
    if (lane < TT) g_logp[(size_t)n * TT + lane] = lg[lane] - ls;
}

// ---------------- CRF NLL forward (warp per batch) ----------------
__global__ __launch_bounds__(128) void crf_forward_k(
    const int* __restrict__ amask,
    const float* __restrict__ start_t, const float* __restrict__ end_t,
    const float* __restrict__ trans)
{
    __shared__ float ts[TT * TT];
    if (threadIdx.x < TT * TT) ts[threadIdx.x] = trans[threadIdx.x];
    __syncthreads();
    const int w = threadIdx.x >> 5, lane = threadIdx.x & 31;
    const int b = blockIdx.x * 4 + w;
    const int* tg = g_labels + b * SS;
    const int* mk = amask + b * SS;
    const float* em = g_logp + (size_t)b * SS * TT;

    int cnt = 0; float num = 0.f;
    for (int s = lane; s < SS; s += 32) {
        int m = mk[s]; cnt += m;
        if (s > 0 && m) num += ts[tg[s - 1] * TT + tg[s]] + em[s * TT + tg[s]];
    }
    if (lane == 0) num += start_t[tg[0]] + em[tg[0]];
#pragma unroll
    for (int o = 16; o; o >>= 1) {
        num += __shfl_xor_sync(0xffffffffu, num, o);
        cnt += __shfl_xor_sync(0xffffffffu, cnt, o);
    }
    if (lane == 0) num += end_t[tg[cnt - 1]];
    num = __shfl_sync(0xffffffffu, num, 0);

    const int j = lane;
    float score = (j < TT) ? start_t[j] + em[j] : -1e30f;
    for (int s = 1; s < SS; s++) {
        float v[TT];
#pragma unroll
        for (int i = 0; i < TT; i++) v[i] = __shfl_sync(0xffffffffu, score, i);
        if (mk[s]) {
            if (j < TT) {
                float vv[TT], m2 = -1e30f;
#pragma unroll
                for (int i = 0; i < TT; i++) { vv[i] = v[i] + ts[i * TT + j]; m2 = fmaxf(m2, vv[i]); }
                float ssum = 0.f;
#pragma unroll
                for (int i = 0; i < TT; i++) ssum += expf(vv[i] - m2);
                score = m2 + logf(ssum) + em[s * TT + j];
            }
        }
    }
    float sc2 = (j < TT) ? score + end_t[j] : -1e30f;
    float vv[TT];
#pragma unroll
    for (int i = 0; i < TT; i++) vv[i] = __shfl_sync(0xffffffffu, sc2, i);
    if (lane == 0) {
        float m2 = vv[0];
#pragma unroll
        for (int i = 1; i < TT; i++) m2 = fmaxf(m2, vv[i]);
        float ssum = 0.f;
#pragma unroll
        for (int i = 0; i < TT; i++) ssum += expf(vv[i] - m2);
        float denom = m2 + logf(ssum);
        g_llh[b] = num - denom;
        g_lenbuf[b] = cnt;
    }
}

// ---------------- Viterbi decode (warp per batch, bp in smem), float32 output ----------------
__global__ __launch_bounds__(128) void viterbi_k(
    const int* __restrict__ amask,
    const float* __restrict__ start_t, const float* __restrict__ end_t,
    const float* __restrict__ trans, float* __restrict__ outp, int navail)
{
    __shared__ float ts[TT * TT];
    __shared__ unsigned char bp[4][SS][TT];
    if (threadIdx.x < TT * TT) ts[threadIdx.x] = trans[threadIdx.x];
    __syncthreads();
    const int w = threadIdx.x >> 5, lane = threadIdx.x & 31;
    const int b = blockIdx.x * 4 + w;
    const int* mk = amask + b * SS;
    const float* em = g_logp + (size_t)b * SS * TT;
    const int j = lane;

    float score = (j < TT) ? start_t[j] + em[j] : -1e30f;
    for (int s = 1; s < SS; s++) {
        float v[TT];
#pragma unroll
        for (int i = 0; i < TT; i++) v[i] = __shfl_sync(0xffffffffu, score, i);
        if (j < TT) {
            int bi = j;
            if (mk[s]) {
                float best = v[0] + ts[0 * TT + j]; bi = 0;
#pragma unroll
                for (int i = 1; i < TT; i++) {
                    float cc = v[i] + ts[i * TT + j];
                    if (cc > best) { best = cc; bi = i; }
                }
                score = best + em[s * TT + j];
            }
            bp[w][s][j] = (unsigned char)bi;
        }
    }
    float sc2 = (j < TT) ? score + end_t[j] : -1e30f;
    float vv[TT];
#pragma unroll
    for (int i = 0; i < TT; i++) vv[i] = __shfl_sync(0xffffffffu, sc2, i);
    if (lane == 0) {
        int tag = 0; float best = vv[0];
#pragma unroll
        for (int i = 1; i < TT; i++) if (vv[i] > best) { best = vv[i]; tag = i; }
        for (int s = SS - 1; s >= 1; s--) {
            int idx = b * SS + s;
            if (idx < navail) outp[idx] = mk[s] ? (float)tag : 0.0f;
            tag = (int)bp[w][s][tag];
        }
        if (b * SS < navail) outp[b * SS] = mk[0] ? (float)tag : 0.0f;
    }
}

// ---------------- finalize loss (float32) ----------------
__global__ void finalize32_k(float* __restrict__ out) {
    const int lane = threadIdx.x;
    float llh = g_llh[lane];
    int len = g_lenbuf[lane];
#pragma unroll
    for (int o = 16; o; o >>= 1) {
        llh += __shfl_xor_sync(0xffffffffu, llh, o);
        len += __shfl_xor_sync(0xffffffffu, len, o);
    }
    if (lane == 0) out[0] = (float)(-(double)llh / (double)len);
}

// ---------------- launch ----------------
extern "C" void kernel_launch(void* const* d_in, const int* in_sizes, int n_in,
                              void* d_out, int out_size) {
    (void)in_sizes; (void)n_in;
    const void* ids    = d_in[0];
    const int*  amask  = (const int*)d_in[1];
    const void* labels = d_in[2];
    const float* emb   = (const float*)d_in[3];
    const float* Wih0  = (const float*)d_in[4];
    const float* Whh0  = (const float*)d_in[5];
    const float* bih0  = (const float*)d_in[6];
    const float* bhh0  = (const float*)d_in[7];
    const float* Wih1  = (const float*)d_in[8];
    const float* Whh1  = (const float*)d_in[9];
    const float* bih1  = (const float*)d_in[10];
    const float* bhh1  = (const float*)d_in[11];
    const float* Wout  = (const float*)d_in[12];
    const float* bout  = (const float*)d_in[13];
    const float* start_t = (const float*)d_in[14];
    const float* end_t   = (const float*)d_in[15];
    const float* trans   = (const float*)d_in[16];
    float* out = (float*)d_out;

    void *p_gates, *p_h0, *p_h1, *p_hT;
    cudaGetSymbolAddress(&p_gates, g_gates);
    cudaGetSymbolAddress(&p_h0, g_h0);
    cudaGetSymbolAddress(&p_h1, g_h1);
    cudaGetSymbolAddress(&p_hT, g_hT);

    cudaFuncSetAttribute(lstm_seq_k, cudaFuncAttributeMaxDynamicSharedMemorySize, SMEM_LSTM_BYTES);
    const int tsm = 768 * 33 * 4;  // 101376
    cudaFuncSetAttribute(transpose_h_k, cudaFuncAttributeMaxDynamicSharedMemorySize, tsm);

    convert_idx_k<<<64, 256>>>(ids, labels);

    dim3 ggrid(48, 128);
    // layer 0
    sgemm_gate_k<<<ggrid, 256>>>(emb, 1, Wih0, bih0, bhh0, (float*)p_gates);
    reset_bar_k<<<1, 1>>>();
    lstm_seq_k<<<128, 768, SMEM_LSTM_BYTES>>>(Whh0, (float*)p_hT);
    transpose_h_k<<<512, 768, tsm>>>((const float*)p_hT, (float*)p_h0);
    // layer 1
    sgemm_gate_k<<<ggrid, 256>>>((const float*)p_h0, 0, Wih1, bih1, bhh1, (float*)p_gates);
    reset_bar_k<<<1, 1>>>();
    lstm_seq_k<<<128, 768, SMEM_LSTM_BYTES>>>(Whh1, (float*)p_hT);
    transpose_h_k<<<512, 768, tsm>>>((const float*)p_hT, (float*)p_h1);

    logits_k<<<2048, 256>>>((const float*)p_h1, Wout, bout);
    crf_forward_k<<<8, 128>>>(amask, start_t, end_t, trans);

    if (out_size >= 1 + MTOT) {
        viterbi_k<<<8, 128>>>(amask, start_t, end_t, trans, out + 1, out_size - 1);
    }
    finalize32_k<<<1, 32>>>(out);
}

// round 11
// speedup vs baseline: 2.8227x; 1.1511x over previous
#include <cuda_runtime.h>
#include <math.h>

#define BB 32
#define SS 512
#define HH 768
#define G4 3072
#define TT 9
#define VV 30522
#define MTOT (BB*SS)       // 16384
#define HT_STRIDE (HH*BB)  // 24576 floats per timestep
#define WPG (384*768*2)    // 589824: gate stride in packed weights (floats)

typedef unsigned long long u64;

// packed fp32x2 ops (sm_103a FFMA2)
#define FMA_F32X2(d, a, b, c) \
    asm("fma.rn.f32x2 %0, %1, %2, %3;" : "=l"(d) : "l"(a), "l"(b), "l"(c))
#define ADD_F32X2(d, a, b) \
    asm("add.rn.f32x2 %0, %1, %2;" : "=l"(d) : "l"(a), "l"(b))
#define PACK_F32X2(out, lo, hi) \
    asm("mov.b64 %0, {%1, %2};" : "=l"(out) : "f"(lo), "f"(hi))
#define UNPACK_F32X2(lo, hi, in) \
    asm("mov.b64 {%0, %1}, %2;" : "=f"(lo), "=f"(hi) : "l"(in))

// ---------------- scratch (device globals; no cudaMalloc allowed) ----------------
__device__ float g_gates[(size_t)MTOT * G4];   // [n][3072] sgemm output (x-part + biases)
__device__ float g_gT[(size_t)MTOT * G4];      // [t][g][j][b] transposed preacts
__device__ float g_h0[(size_t)MTOT * HH];      // layer0 hidden outputs [b*S+t][H]
__device__ float g_h1[(size_t)MTOT * HH];      // layer1 hidden outputs
__device__ float g_hT[(size_t)SS * HT_STRIDE]; // transposed hidden [t][j][b]
__device__ float g_wpack[4 * 384 * 768 * 2];   // [g][jpair][k][(j0,j1)]
__device__ float g_logp[MTOT * TT];            // log-softmax emissions
__device__ int   g_ids[MTOT];
__device__ int   g_labels[MTOT];
__device__ float g_llh[BB];
__device__ int   g_lenbuf[BB];
__device__ unsigned g_bar;                     // global barrier counter (monotonic per layer)

// ---------------- int64/int32 auto-detect + convert (with clamping) ----------------
__global__ void convert_idx_k(const void* __restrict__ idsraw, const void* __restrict__ labraw) {
    int i = blockIdx.x * blockDim.x + threadIdx.x;
    const unsigned* w = (const unsigned*)idsraw;
    bool is64 = true;
#pragma unroll
    for (int k = 0; k < 16; k++) is64 = is64 && (w[2 * k + 1] == 0u);
    if (i < MTOT) {
        long long idv, lbv;
        if (is64) {
            idv = ((const long long*)idsraw)[i];
            lbv = ((const long long*)labraw)[i];
        } else {
            idv = ((const int*)idsraw)[i];
            lbv = ((const int*)labraw)[i];
        }
        int idi = (int)idv, lbi = (int)lbv;
        if (idi < 0) idi = 0; if (idi >= VV) idi = VV - 1;
        if (lbi < 0) lbi = 0; if (lbi >= TT) lbi = TT - 1;
        g_ids[i] = idi;
        g_labels[i] = lbi;
    }
}

__global__ void reset_bar_k() { g_bar = 0u; }

// ---------------- pack Whh -> [g][jpair][k][(j0,j1)] ----------------
__global__ void pack_whh_k(const float* __restrict__ Whh, float* __restrict__ wp) {
    int i = blockIdx.x * 256 + threadIdx.x;
    if (i < 4 * 384 * 768 * 2) {
        int s = i & 1;
        int k = (i >> 1) % 768;
        int jp = ((i >> 1) / 768) % 384;
        int g = i / (768 * 2 * 384);
        wp[i] = Whh[((size_t)(g * 768 + jp * 2 + s)) * 768 + k];
    }
}

// ---------------- transpose gates [n][col] -> gT[t][g][j][b] ----------------
__global__ __launch_bounds__(256) void transpose_gates_k(
    const float* __restrict__ gates, float* __restrict__ gT)
{
    __shared__ float sm[32 * 33];
    const int jt = blockIdx.x;    // 0..23
    const int g  = blockIdx.y;    // 0..3
    const int t  = blockIdx.z;    // 0..511
    const int wi = threadIdx.x >> 5, lane = threadIdx.x & 31;
#pragma unroll
    for (int r = 0; r < 4; r++) {
        int b = wi + r * 8;
        float v = gates[((size_t)(b * SS + t)) * G4 + g * HH + jt * 32 + lane];
        sm[lane * 33 + b] = v;   // sm[j_local][b]
    }
    __syncthreads();
#pragma unroll
    for (int r = 0; r < 4; r++) {
        int jrow = wi + r * 8;
        gT[(((size_t)t * 4 + g) * HH + jt * 32 + jrow) * 32 + lane] = sm[jrow * 33 + lane];
    }
}

// ---------------- SGEMM (f32x2): C[M,3072] = A[M,768] @ W[3072,768]^T + (b1+b2) ----------------
__global__ __launch_bounds__(256) void sgemm_gate_k(
    const float* __restrict__ A, int use_gather,
    const float* __restrict__ W,
    const float* __restrict__ b1, const float* __restrict__ b2,
    float* __restrict__ C)
{
    __shared__ float As[16][132];
    __shared__ float Bs[16][64];
    const int bn = blockIdx.x;
    const int bm = blockIdx.y;
    const int tid = threadIdx.x;
    const int tm = tid >> 4, tn = tid & 15;
    const int row0 = bm * 128;

    const int ar = tid >> 1;
    const int akk = (tid & 1) * 8;
    int grow = row0 + ar;
    if (use_gather) grow = g_ids[grow];
    const float* arow = A + (size_t)grow * HH;
    const int br = tid >> 2;
    const int bkk = (tid & 3) * 4;
    const float* wrow = W + (size_t)(bn * 64 + br) * HH + bkk;

    u64 acc2[4][4];
#pragma unroll
    for (int p = 0; p < 4; p++)
#pragma unroll
        for (int q = 0; q < 4; q++) acc2[p][q] = 0ull;

    for (int k0 = 0; k0 < HH; k0 += 16) {
        float4 a0 = *(const float4*)(arow + k0 + akk);
        float4 a1 = *(const float4*)(arow + k0 + akk + 4);
        float4 bv = *(const float4*)(wrow + k0);
        As[akk + 0][ar] = a0.x; As[akk + 1][ar] = a0.y; As[akk + 2][ar] = a0.z; As[akk + 3][ar] = a0.w;
        As[akk + 4][ar] = a1.x; As[akk + 5][ar] = a1.y; As[akk + 6][ar] = a1.z; As[akk + 7][ar] = a1.w;
        Bs[bkk + 0][br] = bv.x; Bs[bkk + 1][br] = bv.y; Bs[bkk + 2][br] = bv.z; Bs[bkk + 3][br] = bv.w;
        __syncthreads();
#pragma unroll
        for (int kk = 0; kk < 16; kk++) {
            ulonglong2 av0 = *(const ulonglong2*)&As[kk][tm * 8];
            ulonglong2 av1 = *(const ulonglong2*)&As[kk][tm * 8 + 4];
            float4 y = *(const float4*)&Bs[kk][tn * 4];
            u64 ap[4] = {av0.x, av0.y, av1.x, av1.y};
            u64 bd[4];
            PACK_F32X2(bd[0], y.x, y.x);
            PACK_F32X2(bd[1], y.y, y.y);
            PACK_F32X2(bd[2], y.z, y.z);
            PACK_F32X2(bd[3], y.w, y.w);
#pragma unroll
            for (int p = 0; p < 4; p++)
#pragma unroll
                for (int q = 0; q < 4; q++)
                    FMA_F32X2(acc2[p][q], ap[p], bd[q], acc2[p][q]);
        }
        __syncthreads();
    }
    const int col = bn * 64 + tn * 4;
    float bsv[4];
#pragma unroll
    for (int q = 0; q < 4; q++) bsv[q] = b1[col + q] + b2[col + q];
#pragma unroll
    for (int p = 0; p < 4; p++) {
        float lo[4], hi[4];
#pragma unroll
        for (int q = 0; q < 4; q++) UNPACK_F32X2(lo[q], hi[q], acc2[p][q]);
        int gm0 = row0 + tm * 8 + 2 * p;
        float4 o0, o1;
        o0.x = lo[0] + bsv[0]; o0.y = lo[1] + bsv[1]; o0.z = lo[2] + bsv[2]; o0.w = lo[3] + bsv[3];
        o1.x = hi[0] + bsv[0]; o1.y = hi[1] + bsv[1]; o1.z = hi[2] + bsv[2]; o1.w = hi[3] + bsv[3];
        *(float4*)&C[(size_t)gm0 * G4 + col] = o0;
        *(float4*)&C[(size_t)(gm0 + 1) * G4 + col] = o1;
    }
}

// ---------------- Persistent LSTM layer (jpair-packed f32x2, k-major smem) ----------------
// 128 blocks x 768 threads (24 warps). warp w: jpl = w>>3 (0..2), ks = w&7 (0..7).
// Warp computes gate partials for j-pair (j0,j0+1), 4 gates, k-chunk [ks*96, +96). Lane = batch.
// Weights from g_wpack: f32x2 lanes = (j0,j1). Partials exchanged as u64 in smem;
// warps 0..5 do activations for j = base+w (cell state in regs).
#define HS_FLOATS (768 * 33)                       // 25344
#define EX_QWORDS (24 * 4 * 33)                    // 3168 u64
#define SMEM_LSTM_BYTES (HS_FLOATS * 4 + EX_QWORDS * 8)   // 126720 -> 1 block/SM

__global__ __launch_bounds__(768) void lstm_seq_k(float* __restrict__ hT)
{
    extern __shared__ float sm[];
    float* hs = sm;                        // hs[k*33 + b]
    u64* exq = (u64*)(sm + HS_FLOATS);     // exq[(w*4+g)*33 + lane]
    const int tid = threadIdx.x;
    const int w = tid >> 5, lane = tid & 31;
    const int jpl = w >> 3, ks = w & 7;
    const int k0 = ks * 96;
    const float* wp0 = g_wpack + ((size_t)(blockIdx.x * 3 + jpl) * 768 + k0) * 2;
    const bool act = (w < 6);
    const int ja = blockIdx.x * 6 + w;            // activation j (valid if act)
    const int jpa = w >> 1, jsel = w & 1;         // activation partial source
    float c = 0.f;

    for (int t = 0; t < SS; t++) {
        // prefetch preactivations for activation warps (coalesced)
        float pre[4];
        if (act) {
#pragma unroll
            for (int g = 0; g < 4; g++)
                pre[g] = g_gT[(((size_t)t * 4 + g) * HH + ja) * 32 + lane];
        }

        u64 accA[4], accB[4];
#pragma unroll
        for (int g = 0; g < 4; g++) { accA[g] = 0ull; accB[g] = 0ull; }

        if (t > 0) {
            // stage h_{t-1} from hT[t-1][j][b] into hs[k=j][b] (conflict-free scatter)
            const float* src = hT + (size_t)(t - 1) * HT_STRIDE;
#pragma unroll
            for (int r = 0; r < 8; r++) {
                int idx = r * 3072 + tid * 4;
                float4 v = __ldcg((const float4*)(src + idx));
                int jj = idx >> 5, b0 = idx & 31;
                hs[jj * 33 + b0 + 0] = v.x;
                hs[jj * 33 + b0 + 1] = v.y;
                hs[jj * 33 + b0 + 2] = v.z;
                hs[jj * 33 + b0 + 3] = v.w;
            }
            __syncthreads();

            const float* hb = hs + k0 * 33 + lane;
#pragma unroll 8
            for (int kc = 0; kc < 48; kc++) {
                float h0 = hb[(2 * kc) * 33];
                float h1 = hb[(2 * kc + 1) * 33];
                u64 hp0, hp1;
                PACK_F32X2(hp0, h0, h0);
                PACK_F32X2(hp1, h1, h1);
                ulonglong2 w0 = *(const ulonglong2*)(wp0 + 0 * WPG + kc * 4);
                ulonglong2 w1 = *(const ulonglong2*)(wp0 + 1 * WPG + kc * 4);
                ulonglong2 w2 = *(const ulonglong2*)(wp0 + 2 * WPG + kc * 4);
                ulonglong2 w3 = *(const ulonglong2*)(wp0 + 3 * WPG + kc * 4);
                FMA_F32X2(accA[0], w0.x, hp0, accA[0]); FMA_F32X2(accB[0], w0.y, hp1, accB[0]);
                FMA_F32X2(accA[1], w1.x, hp0, accA[1]); FMA_F32X2(accB[1], w1.y, hp1, accB[1]);
                FMA_F32X2(accA[2], w2.x, hp0, accA[2]); FMA_F32X2(accB[2], w2.y, hp1, accB[2]);
                FMA_F32X2(accA[3], w3.x, hp0, accA[3]); FMA_F32X2(accB[3], w3.y, hp1, accB[3]);
            }
        }
        // combine + exchange
#pragma unroll
        for (int g = 0; g < 4; g++) {
            u64 pd;
            ADD_F32X2(pd, accA[g], accB[g]);
            exq[(w * 4 + g) * 33 + lane] = pd;
        }
        __syncthreads();

        if (act) {
            float gt[4];
#pragma unroll
            for (int g = 0; g < 4; g++) {
                float s = pre[g];
#pragma unroll
                for (int p = 0; p < 8; p++) {
                    u64 v = exq[(((jpa * 8 + p) * 4) + g) * 33 + lane];
                    float lo, hi;
                    UNPACK_F32X2(lo, hi, v);
                    s += jsel ? hi : lo;
                }
                gt[g] = s;
            }
            float iv = 1.f / (1.f + expf(-gt[0]));
            float fv = 1.f / (1.f + expf(-gt[1]));
            float gv = tanhf(gt[2]);
            float ov = 1.f / (1.f + expf(-gt[3]));
            c = fv * c + iv * gv;
            float hn = ov * tanhf(c);
            hT[(size_t)t * HT_STRIDE + ja * 32 + lane] = hn;
            __threadfence();   // release: h visible before barrier arrival
        }

        if (t + 1 < SS) {
            __syncthreads();   // all act stores done before tid0 arrives
            if (tid == 0) {
                atomicAdd(&g_bar, 1u);
                const unsigned target = (unsigned)(t + 1) * gridDim.x;
                while (*((volatile unsigned*)&g_bar) < target) __nanosleep(64);
            }
            __syncthreads();
        }
    }
}

// ---------------- transpose g_hT[t][j][b] -> h[n=b*S+t][j] ----------------
__global__ __launch_bounds__(768) void transpose_h_k(
    const float* __restrict__ hT, float* __restrict__ hout)
{
    extern __shared__ float sm[];   // [768][33]
    const int t = blockIdx.x;
    const int tid = threadIdx.x;
#pragma unroll
    for (int r = 0; r < 32; r++) {
        int idx = r * 768 + tid;
        float v = __ldcg(hT + (size_t)t * HT_STRIDE + idx);
        sm[(idx >> 5) * 33 + (idx & 31)] = v;
    }
    __syncthreads();
#pragma unroll
    for (int b = 0; b < 32; b++) {
        hout[((size_t)(b * SS + t)) * HH + tid] = sm[tid * 33 + b];
    }
}

// ---------------- logits + log_softmax ----------------
__global__ __launch_bounds__(256) void logits_k(
    const float* __restrict__ h, const float* __restrict__ Wout, const float* __restrict__ bout)
{
    const int warp = threadIdx.x >> 5, lane = threadIdx.x & 31;
    const int n = blockIdx.x * 8 + warp;
    float a[24];
#pragma unroll
    for (int c = 0; c < 6; c++) {
        float4 v = *(const float4*)(h + (size_t)n * HH + c * 128 + lane * 4);
        a[c * 4 + 0] = v.x; a[c * 4 + 1] = v.y; a[c * 4 + 2] = v.z; a[c * 4 + 3] = v.w;
    }
    float lg[TT];
#pragma unroll
    for (int t = 0; t < TT; t++) {
        float s = 0.f;
#pragma unroll
        for (int c = 0; c < 6; c++) {
            float4 w = *(const float4*)(Wout + (size_t)t * HH + c * 128 + lane * 4);
            s = fmaf(w.x, a[c * 4 + 0], s); s = fmaf(w.y, a[c * 4 + 1], s);
            s = fmaf(w.z, a[c * 4 + 2], s); s = fmaf(w.w, a[c * 4 + 3], s);
        }
#pragma unroll
        for (int o = 16; o; o >>= 1) s += __shfl_xor_sync(0xffffffffu, s, o);
        lg[t] = s + bout[t];
    }
    float m = lg[0];
#pragma unroll
    for (int t = 1; t < TT; t++) m = fmaxf(m, lg[t]);
    float se = 0.f;
#pragma unroll
    for (int t = 0; t < TT; t++) se += expf(lg[t] - m);
    float ls = m + logf(se);
    if (lane < TT) g_logp[(size_t)n * TT + lane] = lg[lane] - ls;
}

// ---------------- CRF NLL forward (warp per batch) ----------------
__global__ __launch_bounds__(128) void crf_forward_k(
    const int* __restrict__ amask,
    const float* __restrict__ start_t, const float* __restrict__ end_t,
    const float* __restrict__ trans)
{
    __shared__ float ts[TT * TT];
    if (threadIdx.x < TT * TT) ts[threadIdx.x] = trans[threadIdx.x];
    __syncthreads();
    const int w = threadIdx.x >> 5, lane = threadIdx.x & 31;
    const int b = blockIdx.x * 4 + w;
    const int* tg = g_labels + b * SS;
    const int* mk = amask + b * SS;
    const float* em = g_logp + (size_t)b * SS * TT;

    int cnt = 0; float num = 0.f;
    for (int s = lane; s < SS; s += 32) {
        int m = mk[s]; cnt += m;
        if (s > 0 && m) num += ts[tg[s - 1] * TT + tg[s]] + em[s * TT + tg[s]];
    }
    if (lane == 0) num += start_t[tg[0]] + em[tg[0]];
#pragma unroll
    for (int o = 16; o; o >>= 1) {
        num += __shfl_xor_sync(0xffffffffu, num, o);
        cnt += __shfl_xor_sync(0xffffffffu, cnt, o);
    }
    if (lane == 0) num += end_t[tg[cnt - 1]];
    num = __shfl_sync(0xffffffffu, num, 0);

    const int j = lane;
    float score = (j < TT) ? start_t[j] + em[j] : -1e30f;
    for (int s = 1; s < SS; s++) {
        float v[TT];
#pragma unroll
        for (int i = 0; i < TT; i++) v[i] = __shfl_sync(0xffffffffu, score, i);
        if (mk[s]) {
            if (j < TT) {
                float vv[TT], m2 = -1e30f;
#pragma unroll
                for (int i = 0; i < TT; i++) { vv[i] = v[i] + ts[i * TT + j]; m2 = fmaxf(m2, vv[i]); }
                float ssum = 0.f;
#pragma unroll
                for (int i = 0; i < TT; i++) ssum += expf(vv[i] - m2);
                score = m2 + logf(ssum) + em[s * TT + j];
            }
        }
    }
    float sc2 = (j < TT) ? score + end_t[j] : -1e30f;
    float vv[TT];
#pragma unroll
    for (int i = 0; i < TT; i++) vv[i] = __shfl_sync(0xffffffffu, sc2, i);
    if (lane == 0) {
        float m2 = vv[0];
#pragma unroll
        for (int i = 1; i < TT; i++) m2 = fmaxf(m2, vv[i]);
        float ssum = 0.f;
#pragma unroll
        for (int i = 0; i < TT; i++) ssum += expf(vv[i] - m2);
        float denom = m2 + logf(ssum);
        g_llh[b] = num - denom;
        g_lenbuf[b] = cnt;
    }
}

// ---------------- Viterbi decode (warp per batch, bp in smem), float32 output ----------------
__global__ __launch_bounds__(128) void viterbi_k(
    const int* __restrict__ amask,
    const float* __restrict__ start_t, const float* __restrict__ end_t,
    const float* __restrict__ trans, float* __restrict__ outp, int navail)
{
    __shared__ float ts[TT * TT];
    __shared__ unsigned char bp[4][SS][TT];
    if (threadIdx.x < TT * TT) ts[threadIdx.x] = trans[threadIdx.x];
    __syncthreads();
    const int w = threadIdx.x >> 5, lane = threadIdx.x & 31;
    const int b = blockIdx.x * 4 + w;
    const int* mk = amask + b * SS;
    const float* em = g_logp + (size_t)b * SS * TT;
    const int j = lane;

    float score = (j < TT) ? start_t[j] + em[j] : -1e30f;
    for (int s = 1; s < SS; s++) {
        float v[TT];
#pragma unroll
        for (int i = 0; i < TT; i++) v[i] = __shfl_sync(0xffffffffu, score, i);
        if (j < TT) {
            int bi = j;
            if (mk[s]) {
                float best = v[0] + ts[0 * TT + j]; bi = 0;
#pragma unroll
                for (int i = 1; i < TT; i++) {
                    float cc = v[i] + ts[i * TT + j];
                    if (cc > best) { best = cc; bi = i; }
                }
                score = best + em[s * TT + j];
            }
            bp[w][s][j] = (unsigned char)bi;
        }
    }
    float sc2 = (j < TT) ? score + end_t[j] : -1e30f;
    float vv[TT];
#pragma unroll
    for (int i = 0; i < TT; i++) vv[i] = __shfl_sync(0xffffffffu, sc2, i);
    if (lane == 0) {
        int tag = 0; float best = vv[0];
#pragma unroll
        for (int i = 1; i < TT; i++) if (vv[i] > best) { best = vv[i]; tag = i; }
        for (int s = SS - 1; s >= 1; s--) {
            int idx = b * SS + s;
            if (idx < navail) outp[idx] = mk[s] ? (float)tag : 0.0f;
            tag = (int)bp[w][s][tag];
        }
        if (b * SS < navail) outp[b * SS] = mk[0] ? (float)tag : 0.0f;
    }
}

// ---------------- finalize loss (float32) ----------------
__global__ void finalize32_k(float* __restrict__ out) {
    const int lane = threadIdx.x;
    float llh = g_llh[lane];
    int len = g_lenbuf[lane];
#pragma unroll
    for (int o = 16; o; o >>= 1) {
        llh += __shfl_xor_sync(0xffffffffu, llh, o);
        len += __shfl_xor_sync(0xffffffffu, len, o);
    }
    if (lane == 0) out[0] = (float)(-(double)llh / (double)len);
}

// ---------------- launch ----------------
extern "C" void kernel_launch(void* const* d_in, const int* in_sizes, int n_in,
                              void* d_out, int out_size) {
    (void)in_sizes; (void)n_in;
    const void* ids    = d_in[0];
    const int*  amask  = (const int*)d_in[1];
    const void* labels = d_in[2];
    const float* emb   = (const float*)d_in[3];
    const float* Wih0  = (const float*)d_in[4];
    const float* Whh0  = (const float*)d_in[5];
    const float* bih0  = (const float*)d_in[6];
    const float* bhh0  = (const float*)d_in[7];
    const float* Wih1  = (const float*)d_in[8];
    const float* Whh1  = (const float*)d_in[9];
    const float* bih1  = (const float*)d_in[10];
    const float* bhh1  = (const float*)d_in[11];
    const float* Wout  = (const float*)d_in[12];
    const float* bout  = (const float*)d_in[13];
    const float* start_t = (const float*)d_in[14];
    const float* end_t   = (const float*)d_in[15];
    const float* trans   = (const float*)d_in[16];
    float* out = (float*)d_out;

    void *p_gates, *p_gT, *p_h0, *p_h1, *p_hT, *p_wp;
    cudaGetSymbolAddress(&p_gates, g_gates);
    cudaGetSymbolAddress(&p_gT, g_gT);
    cudaGetSymbolAddress(&p_h0, g_h0);
    cudaGetSymbolAddress(&p_h1, g_h1);
    cudaGetSymbolAddress(&p_hT, g_hT);
    cudaGetSymbolAddress(&p_wp, g_wpack);

    cudaFuncSetAttribute(lstm_seq_k, cudaFuncAttributeMaxDynamicSharedMemorySize, SMEM_LSTM_BYTES);
    const int tsm = 768 * 33 * 4;  // 101376
    cudaFuncSetAttribute(transpose_h_k, cudaFuncAttributeMaxDynamicSharedMemorySize, tsm);

    convert_idx_k<<<64, 256>>>(ids, labels);

    dim3 ggrid(48, 128);
    dim3 tggrid(24, 4, 512);
    const int packblocks = (4 * 384 * 768 * 2 + 255) / 256;

    // layer 0
    sgemm_gate_k<<<ggrid, 256>>>(emb, 1, Wih0, bih0, bhh0, (float*)p_gates);
    pack_whh_k<<<packblocks, 256>>>(Whh0, (float*)p_wp);
    transpose_gates_k<<<tggrid, 256>>>((const float*)p_gates, (float*)p_gT);
    reset_bar_k<<<1, 1>>>();
    lstm_seq_k<<<128, 768, SMEM_LSTM_BYTES>>>((float*)p_hT);
    transpose_h_k<<<512, 768, tsm>>>((const float*)p_hT, (float*)p_h0);
    // layer 1
    sgemm_gate_k<<<ggrid, 256>>>((const float*)p_h0, 0, Wih1, bih1, bhh1, (float*)p_gates);
    pack_whh_k<<<packblocks, 256>>>(Whh1, (float*)p_wp);
    transpose_gates_k<<<tggrid, 256>>>((const float*)p_gates, (float*)p_gT);
    reset_bar_k<<<1, 1>>>();
    lstm_seq_k<<<128, 768, SMEM_LSTM_BYTES>>>((float*)p_hT);
    transpose_h_k<<<512, 768, tsm>>>((const float*)p_hT, (float*)p_h1);

    logits_k<<<2048, 256>>>((const float*)p_h1, Wout, bout);
    crf_forward_k<<<8, 128>>>(amask, start_t, end_t, trans);

    if (out_size >= 1 + MTOT) {
        viterbi_k<<<8, 128>>>(amask, start_t, end_t, trans, out + 1, out_size - 1);
    }
    finalize32_k<<<1, 32>>>(out);
}

// round 12
// speedup vs baseline: 3.8736x; 1.3723x over previous
#include <cuda_runtime.h>
#include <math.h>

#define BB 32
#define SS 512
#define HH 768
#define G4 3072
#define TT 9
#define VV 30522
#define MTOT (BB*SS)       // 16384
#define HT_STRIDE (HH*BB)  // 24576 floats per timestep

typedef unsigned long long u64;

// packed fp32x2 ops (sm_103a FFMA2)
#define FMA_F32X2(d, a, b, c) \
    asm("fma.rn.f32x2 %0, %1, %2, %3;" : "=l"(d) : "l"(a), "l"(b), "l"(c))
#define ADD_F32X2(d, a, b) \
    asm("add.rn.f32x2 %0, %1, %2;" : "=l"(d) : "l"(a), "l"(b))
#define PACK_F32X2(out, lo, hi) \
    asm("mov.b64 %0, {%1, %2};" : "=l"(out) : "f"(lo), "f"(hi))
#define UNPACK_F32X2(lo, hi, in) \
    asm("mov.b64 {%0, %1}, %2;" : "=f"(lo), "=f"(hi) : "l"(in))

// ---------------- scratch (device globals; no cudaMalloc allowed) ----------------
__device__ float g_gates[(size_t)MTOT * G4];   // [n][3072] sgemm output (x-part + biases)
__device__ float g_gT[(size_t)MTOT * G4];      // [t][g][j][b] transposed preacts
__device__ float g_h0[(size_t)MTOT * HH];      // layer0 hidden outputs [b*S+t][H]
__device__ float g_h1[(size_t)MTOT * HH];      // layer1 hidden outputs
__device__ float g_hT[(size_t)SS * HT_STRIDE]; // transposed hidden [t][j][b]
__device__ float g_wpack[4 * 384 * 768 * 2];   // [g][jpair][k][(j0,j1)]
__device__ float g_logp[MTOT * TT];            // log-softmax emissions
__device__ int   g_ids[MTOT];
__device__ int   g_labels[MTOT];
__device__ float g_llh[BB];
__device__ int   g_lenbuf[BB];
__device__ unsigned g_bar;                     // global barrier counter (monotonic per layer)

// ---------------- int64/int32 auto-detect + convert (with clamping) ----------------
__global__ void convert_idx_k(const void* __restrict__ idsraw, const void* __restrict__ labraw) {
    int i = blockIdx.x * blockDim.x + threadIdx.x;
    const unsigned* w = (const unsigned*)idsraw;
    bool is64 = true;
#pragma unroll
    for (int k = 0; k < 16; k++) is64 = is64 && (w[2 * k + 1] == 0u);
    if (i < MTOT) {
        long long idv, lbv;
        if (is64) {
            idv = ((const long long*)idsraw)[i];
            lbv = ((const long long*)labraw)[i];
        } else {
            idv = ((const int*)idsraw)[i];
            lbv = ((const int*)labraw)[i];
        }
        int idi = (int)idv, lbi = (int)lbv;
        if (idi < 0) idi = 0; if (idi >= VV) idi = VV - 1;
        if (lbi < 0) lbi = 0; if (lbi >= TT) lbi = TT - 1;
        g_ids[i] = idi;
        g_labels[i] = lbi;
    }
}

__global__ void reset_bar_k() { g_bar = 0u; }

// ---------------- pack Whh -> [g][jpair][k][(j0,j1)] ----------------
__global__ void pack_whh_k(const float* __restrict__ Whh, float* __restrict__ wp) {
    int i = blockIdx.x * 256 + threadIdx.x;
    if (i < 4 * 384 * 768 * 2) {
        int s = i & 1;
        int k = (i >> 1) % 768;
        int jp = ((i >> 1) / 768) % 384;
        int g = i / (768 * 2 * 384);
        wp[i] = Whh[((size_t)(g * 768 + jp * 2 + s)) * 768 + k];
    }
}

// ---------------- transpose gates [n][col] -> gT[t][g][j][b] ----------------
__global__ __launch_bounds__(256) void transpose_gates_k(
    const float* __restrict__ gates, float* __restrict__ gT)
{
    __shared__ float sm[32 * 33];
    const int jt = blockIdx.x;    // 0..23
    const int g  = blockIdx.y;    // 0..3
    const int t  = blockIdx.z;    // 0..511
    const int wi = threadIdx.x >> 5, lane = threadIdx.x & 31;
#pragma unroll
    for (int r = 0; r < 4; r++) {
        int b = wi + r * 8;
        float v = gates[((size_t)(b * SS + t)) * G4 + g * HH + jt * 32 + lane];
        sm[lane * 33 + b] = v;   // sm[j_local][b]
    }
    __syncthreads();
#pragma unroll
    for (int r = 0; r < 4; r++) {
        int jrow = wi + r * 8;
        gT[(((size_t)t * 4 + g) * HH + jt * 32 + jrow) * 32 + lane] = sm[jrow * 33 + lane];
    }
}

// ---------------- SGEMM (f32x2): C[M,3072] = A[M,768] @ W[3072,768]^T + (b1+b2) ----------------
__global__ __launch_bounds__(256) void sgemm_gate_k(
    const float* __restrict__ A, int use_gather,
    const float* __restrict__ W,
    const float* __restrict__ b1, const float* __restrict__ b2,
    float* __restrict__ C)
{
    __shared__ float As[16][132];
    __shared__ float Bs[16][64];
    const int bn = blockIdx.x;
    const int bm = blockIdx.y;
    const int tid = threadIdx.x;
    const int tm = tid >> 4, tn = tid & 15;
    const int row0 = bm * 128;

    const int ar = tid >> 1;
    const int akk = (tid & 1) * 8;
    int grow = row0 + ar;
    if (use_gather) grow = g_ids[grow];
    const float* arow = A + (size_t)grow * HH;
    const int br = tid >> 2;
    const int bkk = (tid & 3) * 4;
    const float* wrow = W + (size_t)(bn * 64 + br) * HH + bkk;

    u64 acc2[4][4];
#pragma unroll
    for (int p = 0; p < 4; p++)
#pragma unroll
        for (int q = 0; q < 4; q++) acc2[p][q] = 0ull;

    for (int k0 = 0; k0 < HH; k0 += 16) {
        float4 a0 = *(const float4*)(arow + k0 + akk);
        float4 a1 = *(const float4*)(arow + k0 + akk + 4);
        float4 bv = *(const float4*)(wrow + k0);
        As[akk + 0][ar] = a0.x; As[akk + 1][ar] = a0.y; As[akk + 2][ar] = a0.z; As[akk + 3][ar] = a0.w;
        As[akk + 4][ar] = a1.x; As[akk + 5][ar] = a1.y; As[akk + 6][ar] = a1.z; As[akk + 7][ar] = a1.w;
        Bs[bkk + 0][br] = bv.x; Bs[bkk + 1][br] = bv.y; Bs[bkk + 2][br] = bv.z; Bs[bkk + 3][br] = bv.w;
        __syncthreads();
#pragma unroll
        for (int kk = 0; kk < 16; kk++) {
            ulonglong2 av0 = *(const ulonglong2*)&As[kk][tm * 8];
            ulonglong2 av1 = *(const ulonglong2*)&As[kk][tm * 8 + 4];
            float4 y = *(const float4*)&Bs[kk][tn * 4];
            u64 ap[4] = {av0.x, av0.y, av1.x, av1.y};
            u64 bd[4];
            PACK_F32X2(bd[0], y.x, y.x);
            PACK_F32X2(bd[1], y.y, y.y);
            PACK_F32X2(bd[2], y.z, y.z);
            PACK_F32X2(bd[3], y.w, y.w);
#pragma unroll
            for (int p = 0; p < 4; p++)
#pragma unroll
                for (int q = 0; q < 4; q++)
                    FMA_F32X2(acc2[p][q], ap[p], bd[q], acc2[p][q]);
        }
        __syncthreads();
    }
    const int col = bn * 64 + tn * 4;
    float bsv[4];
#pragma unroll
    for (int q = 0; q < 4; q++) bsv[q] = b1[col + q] + b2[col + q];
#pragma unroll
    for (int p = 0; p < 4; p++) {
        float lo[4], hi[4];
#pragma unroll
        for (int q = 0; q < 4; q++) UNPACK_F32X2(lo[q], hi[q], acc2[p][q]);
        int gm0 = row0 + tm * 8 + 2 * p;
        float4 o0, o1;
        o0.x = lo[0] + bsv[0]; o0.y = lo[1] + bsv[1]; o0.z = lo[2] + bsv[2]; o0.w = lo[3] + bsv[3];
        o1.x = hi[0] + bsv[0]; o1.y = hi[1] + bsv[1]; o1.z = hi[2] + bsv[2]; o1.w = hi[3] + bsv[3];
        *(float4*)&C[(size_t)gm0 * G4 + col] = o0;
        *(float4*)&C[(size_t)(gm0 + 1) * G4 + col] = o1;
    }
}

// ---------------- Persistent LSTM layer (weights in SMEM, jpair f32x2) ----------------
// 128 blocks x 768 threads (24 warps). warp w: jpl = w>>3 (0..2), ks = w&7 (0..7).
// Weights for this block's 3 jpairs x 4 gates x 768 k are preloaded into smem ONCE:
// immune to the per-step gpu-fence L1 flush. Lane = batch.
#define WS_FLOATS (3 * 4 * 768 * 2)                // 18432 floats = 73728 B
#define HS_FLOATS (768 * 33)                       // 25344 floats = 101376 B
#define EX_QWORDS (24 * 4 * 33)                    // 3168 u64 = 25344 B
#define SMEM_LSTM_BYTES ((WS_FLOATS + HS_FLOATS) * 4 + EX_QWORDS * 8)   // 200448 B

__global__ __launch_bounds__(768) void lstm_seq_k(float* __restrict__ hT)
{
    extern __shared__ float sm[];
    float* ws = sm;                                   // [jpl][g][k][2]
    float* hs = sm + WS_FLOATS;                       // hs[k*33 + b]
    u64* exq = (u64*)(sm + WS_FLOATS + HS_FLOATS);    // exq[(w*4+g)*33 + lane]
    const int tid = threadIdx.x;
    const int w = tid >> 5, lane = tid & 31;
    const int jpl = w >> 3, ks = w & 7;
    const int k0 = ks * 96;
    const bool act = (w < 6);
    const int ja = blockIdx.x * 6 + w;            // activation j (valid if act)
    const int jpa = w >> 1, jsel = w & 1;         // activation partial source
    float c = 0.f;

    // ---- one-time weight preload: g_wpack[(g*384 + bx*3 + jpl)*1536 + q4] -> ws[(jpl*4+g)*1536 + q4]
    {
        const float4* src4 = (const float4*)g_wpack;
        float4* dst4 = (float4*)ws;
#pragma unroll
        for (int it = 0; it < 6; it++) {
            int i = it * 768 + tid;         // 0..4607 float4s
            int chunk = i / 384;            // 0..11 = jpl*4+g
            int q = i - chunk * 384;
            int cjpl = chunk >> 2, cg = chunk & 3;
            dst4[chunk * 384 + q] = src4[(size_t)(cg * 384 + blockIdx.x * 3 + cjpl) * 384 + q];
        }
    }
    __syncthreads();

    const float* wbase = ws + (jpl * 4) * 1536 + k0 * 2;   // gate g at +g*1536

    for (int t = 0; t < SS; t++) {
        // prefetch preactivations for activation warps (coalesced)
        float pre[4];
        if (act) {
#pragma unroll
            for (int g = 0; g < 4; g++)
                pre[g] = g_gT[(((size_t)t * 4 + g) * HH + ja) * 32 + lane];
        }

        u64 accA[4], accB[4];
#pragma unroll
        for (int g = 0; g < 4; g++) { accA[g] = 0ull; accB[g] = 0ull; }

        if (t > 0) {
            // stage h_{t-1} from hT[t-1][j][b] into hs[k=j][b] (conflict-free scatter)
            const float* src = hT + (size_t)(t - 1) * HT_STRIDE;
#pragma unroll
            for (int r = 0; r < 8; r++) {
                int idx = r * 3072 + tid * 4;
                float4 v = __ldcg((const float4*)(src + idx));
                int jj = idx >> 5, b0 = idx & 31;
                hs[jj * 33 + b0 + 0] = v.x;
                hs[jj * 33 + b0 + 1] = v.y;
                hs[jj * 33 + b0 + 2] = v.z;
                hs[jj * 33 + b0 + 3] = v.w;
            }
            __syncthreads();

            const float* hb = hs + k0 * 33 + lane;
#pragma unroll 8
            for (int kc = 0; kc < 48; kc++) {
                float h0 = hb[(2 * kc) * 33];
                float h1 = hb[(2 * kc + 1) * 33];
                u64 hp0, hp1;
                PACK_F32X2(hp0, h0, h0);
                PACK_F32X2(hp1, h1, h1);
                ulonglong2 w0 = *(const ulonglong2*)(wbase + 0 * 1536 + kc * 4);
                ulonglong2 w1 = *(const ulonglong2*)(wbase + 1 * 1536 + kc * 4);
                ulonglong2 w2 = *(const ulonglong2*)(wbase + 2 * 1536 + kc * 4);
                ulonglong2 w3 = *(const ulonglong2*)(wbase + 3 * 1536 + kc * 4);
                FMA_F32X2(accA[0], w0.x, hp0, accA[0]); FMA_F32X2(accB[0], w0.y, hp1, accB[0]);
                FMA_F32X2(accA[1], w1.x, hp0, accA[1]); FMA_F32X2(accB[1], w1.y, hp1, accB[1]);
                FMA_F32X2(accA[2], w2.x, hp0, accA[2]); FMA_F32X2(accB[2], w2.y, hp1, accB[2]);
                FMA_F32X2(accA[3], w3.x, hp0, accA[3]); FMA_F32X2(accB[3], w3.y, hp1, accB[3]);
            }
        }
        // combine + exchange
#pragma unroll
        for (int g = 0; g < 4; g++) {
            u64 pd;
            ADD_F32X2(pd, accA[g], accB[g]);
            exq[(w * 4 + g) * 33 + lane] = pd;
        }
        __syncthreads();

        if (act) {
            float gt[4];
#pragma unroll
            for (int g = 0; g < 4; g++) {
                float s = pre[g];
#pragma unroll
                for (int p = 0; p < 8; p++) {
                    u64 v = exq[(((jpa * 8 + p) * 4) + g) * 33 + lane];
                    float lo, hi;
                    UNPACK_F32X2(lo, hi, v);
                    s += jsel ? hi : lo;
                }
                gt[g] = s;
            }
            float iv = 1.f / (1.f + expf(-gt[0]));
            float fv = 1.f / (1.f + expf(-gt[1]));
            float gv = tanhf(gt[2]);
            float ov = 1.f / (1.f + expf(-gt[3]));
            c = fv * c + iv * gv;
            float hn = ov * tanhf(c);
            hT[(size_t)t * HT_STRIDE + ja * 32 + lane] = hn;
        }

        if (t + 1 < SS) {
            __syncthreads();   // all h stores done (CTA-scope) before tid0's fence
            if (tid == 0) {
                __threadfence();   // gpu-scope release (cumulative over bar.sync)
                atomicAdd(&g_bar, 1u);
                const unsigned target = (unsigned)(t + 1) * gridDim.x;
                while (*((volatile unsigned*)&g_bar) < target) __nanosleep(64);
            }
            __syncthreads();
        }
    }
}

// ---------------- transpose g_hT[t][j][b] -> h[n=b*S+t][j] ----------------
__global__ __launch_bounds__(768) void transpose_h_k(
    const float* __restrict__ hT, float* __restrict__ hout)
{
    extern __shared__ float sm[];   // [768][33]
    const int t = blockIdx.x;
    const int tid = threadIdx.x;
#pragma unroll
    for (int r = 0; r < 32; r++) {
        int idx = r * 768 + tid;
        float v = __ldcg(hT + (size_t)t * HT_STRIDE + idx);
        sm[(idx >> 5) * 33 + (idx & 31)] = v;
    }
    __syncthreads();
#pragma unroll
    for (int b = 0; b < 32; b++) {
        hout[((size_t)(b * SS + t)) * HH + tid] = sm[tid * 33 + b];
    }
}

// ---------------- logits + log_softmax ----------------
__global__ __launch_bounds__(256) void logits_k(
    const float* __restrict__ h, const float* __restrict__ Wout, const float* __restrict__ bout)
{
    const int warp = threadIdx.x >> 5, lane = threadIdx.x & 31;
    const int n = blockIdx.x * 8 + warp;
    float a[24];
#pragma unroll
    for (int c = 0; c < 6; c++) {
        float4 v = *(const float4*)(h + (size_t)n * HH + c * 128 + lane * 4);
        a[c * 4 + 0] = v.x; a[c * 4 + 1] = v.y; a[c * 4 + 2] = v.z; a[c * 4 + 3] = v.w;
    }
    float lg[TT];
#pragma unroll
    for (int t = 0; t < TT; t++) {
        float s = 0.f;
#pragma unroll
        for (int c = 0; c < 6; c++) {
            float4 w = *(const float4*)(Wout + (size_t)t * HH + c * 128 + lane * 4);
            s = fmaf(w.x, a[c * 4 + 0], s); s = fmaf(w.y, a[c * 4 + 1], s);
            s = fmaf(w.z, a[c * 4 + 2], s); s = fmaf(w.w, a[c * 4 + 3], s);
        }
#pragma unroll
        for (int o = 16; o; o >>= 1) s += __shfl_xor_sync(0xffffffffu, s, o);
        lg[t] = s + bout[t];
    }
    float m = lg[0];
#pragma unroll
    for (int t = 1; t < TT; t++) m = fmaxf(m, lg[t]);
    float se = 0.f;
#pragma unroll
    for (int t = 0; t < TT; t++) se += expf(lg[t] - m);
    float ls = m + logf(se);
    if (lane < TT) g_logp[(size_t)n * TT + lane] = lg[lane] - ls;
}

// ---------------- CRF NLL forward (warp per batch) ----------------
__global__ __launch_bounds__(128) void crf_forward_k(
    const int* __restrict__ amask,
    const float* __restrict__ start_t, const float* __restrict__ end_t,
    const float* __restrict__ trans)
{
    __shared__ float ts[TT * TT];
    if (threadIdx.x < TT * TT) ts[threadIdx.x] = trans[threadIdx.x];
    __syncthreads();
    const int w = threadIdx.x >> 5, lane = threadIdx.x & 31;
    const int b = blockIdx.x * 4 + w;
    const int* tg = g_labels + b * SS;
    const int* mk = amask + b * SS;
    const float* em = g_logp + (size_t)b * SS * TT;

    int cnt = 0; float num = 0.f;
    for (int s = lane; s < SS; s += 32) {
        int m = mk[s]; cnt += m;
        if (s > 0 && m) num += ts[tg[s - 1] * TT + tg[s]] + em[s * TT + tg[s]];
    }
    if (lane == 0) num += start_t[tg[0]] + em[tg[0]];
#pragma unroll
    for (int o = 16; o; o >>= 1) {
        num += __shfl_xor_sync(0xffffffffu, num, o);
        cnt += __shfl_xor_sync(0xffffffffu, cnt, o);
    }
    if (lane == 0) num += end_t[tg[cnt - 1]];
    num = __shfl_sync(0xffffffffu, num, 0);

    const int j = lane;
    float score = (j < TT) ? start_t[j] + em[j] : -1e30f;
    for (int s = 1; s < SS; s++) {
        float v[TT];
#pragma unroll
        for (int i = 0; i < TT; i++) v[i] = __shfl_sync(0xffffffffu, score, i);
        if (mk[s]) {
            if (j < TT) {
                float vv[TT], m2 = -1e30f;
#pragma unroll
                for (int i = 0; i < TT; i++) { vv[i] = v[i] + ts[i * TT + j]; m2 = fmaxf(m2, vv[i]); }
                float ssum = 0.f;
#pragma unroll
                for (int i = 0; i < TT; i++) ssum += expf(vv[i] - m2);
                score = m2 + logf(ssum) + em[s * TT + j];
            }
        }
    }
    float sc2 = (j < TT) ? score + end_t[j] : -1e30f;
    float vv[TT];
#pragma unroll
    for (int i = 0; i < TT; i++) vv[i] = __shfl_sync(0xffffffffu, sc2, i);
    if (lane == 0) {
        float m2 = vv[0];
#pragma unroll
        for (int i = 1; i < TT; i++) m2 = fmaxf(m2, vv[i]);
        float ssum = 0.f;
#pragma unroll
        for (int i = 0; i < TT; i++) ssum += expf(vv[i] - m2);
        float denom = m2 + logf(ssum);
        g_llh[b] = num - denom;
        g_lenbuf[b] = cnt;
    }
}

// ---------------- Viterbi decode (warp per batch, bp in smem), float32 output ----------------
__global__ __launch_bounds__(128) void viterbi_k(
    const int* __restrict__ amask,
    const float* __restrict__ start_t, const float* __restrict__ end_t,
    const float* __restrict__ trans, float* __restrict__ outp, int navail)
{
    __shared__ float ts[TT * TT];
    __shared__ unsigned char bp[4][SS][TT];
    if (threadIdx.x < TT * TT) ts[threadIdx.x] = trans[threadIdx.x];
    __syncthreads();
    const int w = threadIdx.x >> 5, lane = threadIdx.x & 31;
    const int b = blockIdx.x * 4 + w;
    const int* mk = amask + b * SS;
    const float* em = g_logp + (size_t)b * SS * TT;
    const int j = lane;

    float score = (j < TT) ? start_t[j] + em[j] : -1e30f;
    for (int s = 1; s < SS; s++) {
        float v[TT];
#pragma unroll
        for (int i = 0; i < TT; i++) v[i] = __shfl_sync(0xffffffffu, score, i);
        if (j < TT) {
            int bi = j;
            if (mk[s]) {
                float best = v[0] + ts[0 * TT + j]; bi = 0;
#pragma unroll
                for (int i = 1; i < TT; i++) {
                    float cc = v[i] + ts[i * TT + j];
                    if (cc > best) { best = cc; bi = i; }
                }
                score = best + em[s * TT + j];
            }
            bp[w][s][j] = (unsigned char)bi;
        }
    }
    float sc2 = (j < TT) ? score + end_t[j] : -1e30f;
    float vv[TT];
#pragma unroll
    for (int i = 0; i < TT; i++) vv[i] = __shfl_sync(0xffffffffu, sc2, i);
    if (lane == 0) {
        int tag = 0; float best = vv[0];
#pragma unroll
        for (int i = 1; i < TT; i++) if (vv[i] > best) { best = vv[i]; tag = i; }
        for (int s = SS - 1; s >= 1; s--) {
            int idx = b * SS + s;
            if (idx < navail) outp[idx] = mk[s] ? (float)tag : 0.0f;
            tag = (int)bp[w][s][tag];
        }
        if (b * SS < navail) outp[b * SS] = mk[0] ? (float)tag : 0.0f;
    }
}

// ---------------- finalize loss (float32) ----------------
__global__ void finalize32_k(float* __restrict__ out) {
    const int lane = threadIdx.x;
    float llh = g_llh[lane];
    int len = g_lenbuf[lane];
#pragma unroll
    for (int o = 16; o; o >>= 1) {
        llh += __shfl_xor_sync(0xffffffffu, llh, o);
        len += __shfl_xor_sync(0xffffffffu, len, o);
    }
    if (lane == 0) out[0] = (float)(-(double)llh / (double)len);
}

// ---------------- launch ----------------
extern "C" void kernel_launch(void* const* d_in, const int* in_sizes, int n_in,
                              void* d_out, int out_size) {
    (void)in_sizes; (void)n_in;
    const void* ids    = d_in[0];
    const int*  amask  = (const int*)d_in[1];
    const void* labels = d_in[2];
    const float* emb   = (const float*)d_in[3];
    const float* Wih0  = (const float*)d_in[4];
    const float* Whh0  = (const float*)d_in[5];
    const float* bih0  = (const float*)d_in[6];
    const float* bhh0  = (const float*)d_in[7];
    const float* Wih1  = (const float*)d_in[8];
    const float* Whh1  = (const float*)d_in[9];
    const float* bih1  = (const float*)d_in[10];
    const float* bhh1  = (const float*)d_in[11];
    const float* Wout  = (const float*)d_in[12];
    const float* bout  = (const float*)d_in[13];
    const float* start_t = (const float*)d_in[14];
    const float* end_t   = (const float*)d_in[15];
    const float* trans   = (const float*)d_in[16];
    float* out = (float*)d_out;

    void *p_gates, *p_gT, *p_h0, *p_h1, *p_hT, *p_wp;
    cudaGetSymbolAddress(&p_gates, g_gates);
    cudaGetSymbolAddress(&p_gT, g_gT);
    cudaGetSymbolAddress(&p_h0, g_h0);
    cudaGetSymbolAddress(&p_h1, g_h1);
    cudaGetSymbolAddress(&p_hT, g_hT);
    cudaGetSymbolAddress(&p_wp, g_wpack);

    cudaFuncSetAttribute(lstm_seq_k, cudaFuncAttributeMaxDynamicSharedMemorySize, SMEM_LSTM_BYTES);
    const int tsm = 768 * 33 * 4;  // 101376
    cudaFuncSetAttribute(transpose_h_k, cudaFuncAttributeMaxDynamicSharedMemorySize, tsm);

    convert_idx_k<<<64, 256>>>(ids, labels);

    dim3 ggrid(48, 128);
    dim3 tggrid(24, 4, 512);
    const int packblocks = (4 * 384 * 768 * 2 + 255) / 256;

    // layer 0
    sgemm_gate_k<<<ggrid, 256>>>(emb, 1, Wih0, bih0, bhh0, (float*)p_gates);
    pack_whh_k<<<packblocks, 256>>>(Whh0, (float*)p_wp);
    transpose_gates_k<<<tggrid, 256>>>((const float*)p_gates, (float*)p_gT);
    reset_bar_k<<<1, 1>>>();
    lstm_seq_k<<<128, 768, SMEM_LSTM_BYTES>>>((float*)p_hT);
    transpose_h_k<<<512, 768, tsm>>>((const float*)p_hT, (float*)p_h0);
    // layer 1
    sgemm_gate_k<<<ggrid, 256>>>((const float*)p_h0, 0, Wih1, bih1, bhh1, (float*)p_gates);
    pack_whh_k<<<packblocks, 256>>>(Whh1, (float*)p_wp);
    transpose_gates_k<<<tggrid, 256>>>((const float*)p_gates, (float*)p_gT);
    reset_bar_k<<<1, 1>>>();
    lstm_seq_k<<<128, 768, SMEM_LSTM_BYTES>>>((float*)p_hT);
    transpose_h_k<<<512, 768, tsm>>>((const float*)p_hT, (float*)p_h1);

    logits_k<<<2048, 256>>>((const float*)p_h1, Wout, bout);
    crf_forward_k<<<8, 128>>>(amask, start_t, end_t, trans);

    if (out_size >= 1 + MTOT) {
        viterbi_k<<<8, 128>>>(amask, start_t, end_t, trans, out + 1, out_size - 1);
    }
    finalize32_k<<<1, 32>>>(out);
}